// round 5
// baseline (speedup 1.0000x reference)
#include <cuda_runtime.h>
#include <math.h>

#define HW 16384

// Scratch (module-load allocated, legal per harness rules)
__device__ float g_om [4 * 216 * HW];   // offset/mask conv output
__device__ float g_em1[4 *  64 * HW];   // em intermediate
__device__ float g_em [4 *  72 * HW];   // em mask (sigmoid)

// ---------------------------------------------------------------------------
// Direct 3x3 conv, stride 1, pad 1, H=W=128, NCHW fp32, packed-f32x2 math.
// Block: 256 threads -> 64(w) x 32(h) output tile, 8 output channels.
// Thread: 8 pixels (tx, tx+32) x (ty, ty+8, ty+16, ty+24), 8 co packed as
// 4 f32x2 pairs -> 32 packed accumulators (64 regs).
// Weights staged in smem co-contiguous so a co-pair is one broadcast LDS.64.
// Input channels streamed through smem in chunks of 4.
// ACT: 0 = none, 1 = leaky(0.1), 2 = sigmoid.  Channel-concat via (in1,cin1)+in2.
// ---------------------------------------------------------------------------
template <int ACT>
__global__ __launch_bounds__(256, 2) void conv3x3_f2_kernel(
    const float* __restrict__ in1, const float* __restrict__ in2,
    int cin1, int cin,
    const float* __restrict__ wgt, const float* __restrict__ bias,
    float* __restrict__ out, int cout)
{
    __shared__ float s_in[4][34][66];                    // 35.9 KB
    __shared__ unsigned long long s_w2[4][9][4];         // [ci][k][co-pair]

    const int tid = threadIdx.x;
    const int co_tiles = cout >> 3;
    const int b   = blockIdx.z / co_tiles;
    const int co0 = (blockIdx.z % co_tiles) << 3;
    const int h0  = blockIdx.y * 32;
    const int w0  = blockIdx.x * 64;
    const int tx  = tid & 31;
    const int ty  = tid >> 5;     // 0..7

    unsigned long long acc[8][4];
#pragma unroll
    for (int i = 0; i < 8; i++)
#pragma unroll
        for (int p = 0; p < 4; p++) acc[i][p] = 0ull;

    const int nchunks = cin >> 2;
    for (int cb = 0; cb < nchunks; cb++) {
        const int c0 = cb << 2;
        // stage 4 x 34 x 66 input tile (zero-padded borders)
        for (int i = tid; i < 4 * 34 * 66; i += 256) {
            int ci = i / 2244;
            int r  = i - ci * 2244;
            int yy = r / 66;
            int xx = r - yy * 66;
            int gh = h0 - 1 + yy;
            int gw = w0 - 1 + xx;
            int c  = c0 + ci;
            float v = 0.f;
            if (gh >= 0 && gh < 128 && gw >= 0 && gw < 128) {
                const float* p = (c < cin1)
                    ? (in1 + ((size_t)b * cin1 + c) * HW)
                    : (in2 + ((size_t)b * (cin - cin1) + (c - cin1)) * HW);
                v = p[gh * 128 + gw];
            }
            s_in[ci][yy][xx] = v;
        }
        // stage weights: layout [ci][k][o] with o contiguous (288 floats)
        // NOTE: 288 > 256 threads -> MUST grid-stride (R4 bug: `if (tid<288)`
        // left floats 256..287 unwritten)
        for (int i = tid; i < 288; i += 256) {
            int ci = i / 72;
            int r  = i - ci * 72;
            int k  = r >> 3;
            int o  = r & 7;
            ((float*)s_w2)[i] =
                wgt[((size_t)(co0 + o) * cin + (c0 + ci)) * 9 + k];
        }
        __syncthreads();

#pragma unroll 1
        for (int ci = 0; ci < 4; ci++) {
#pragma unroll
            for (int ky = 0; ky < 3; ky++) {
#pragma unroll
                for (int kx = 0; kx < 3; kx++) {
                    unsigned long long wv[4];
#pragma unroll
                    for (int p = 0; p < 4; p++)
                        wv[p] = s_w2[ci][ky * 3 + kx][p];
#pragma unroll
                    for (int sy = 0; sy < 4; sy++) {
#pragma unroll
                        for (int sx = 0; sx < 2; sx++) {
                            float v = s_in[ci][ty + 8 * sy + ky][tx + 32 * sx + kx];
                            unsigned long long vv;
                            asm("mov.b64 %0, {%1, %1};"
                                : "=l"(vv) : "r"(__float_as_uint(v)));
#pragma unroll
                            for (int p = 0; p < 4; p++)
                                asm("fma.rn.f32x2 %0, %1, %2, %0;"
                                    : "+l"(acc[sy * 2 + sx][p])
                                    : "l"(vv), "l"(wv[p]));
                        }
                    }
                }
            }
        }
        __syncthreads();
    }

    float bs[8];
#pragma unroll
    for (int o = 0; o < 8; o++) bs[o] = bias[co0 + o];

#pragma unroll
    for (int sy = 0; sy < 4; sy++) {
#pragma unroll
        for (int sx = 0; sx < 2; sx++) {
            int hh = h0 + ty + 8 * sy;
            int ww = w0 + tx + 32 * sx;
#pragma unroll
            for (int p = 0; p < 4; p++) {
                unsigned long long a = acc[sy * 2 + sx][p];
                float v0 = __uint_as_float((unsigned)(a & 0xffffffffu)) + bs[2 * p];
                float v1 = __uint_as_float((unsigned)(a >> 32)) + bs[2 * p + 1];
                if (ACT == 1) { v0 = (v0 >= 0.f) ? v0 : 0.1f * v0;
                                v1 = (v1 >= 0.f) ? v1 : 0.1f * v1; }
                if (ACT == 2) { v0 = 1.f / (1.f + expf(-v0));
                                v1 = 1.f / (1.f + expf(-v1)); }
                out[((size_t)b * cout + co0 + 2 * p) * HW + hh * 128 + ww] = v0;
                out[((size_t)b * cout + co0 + 2 * p + 1) * HW + hh * 128 + ww] = v1;
            }
        }
    }
}

// ---------------------------------------------------------------------------
// Fused dual modulated deformable conv (DCNv2), stride 1, pad 1.
// offsets/mask straight from g_om (offset = om[:, :144] verbatim):
//   dy = om[b, 2*(g*9+kk)], dx = om[b, 2*(g*9+kk)+1], mx = sigmoid(om[b,144+g*9+kk])
// second mask from g_em. Both outputs share offsets + w_dc.
// ---------------------------------------------------------------------------
__global__ __launch_bounds__(256) void deform_kernel(
    const float* __restrict__ x, const float* __restrict__ s,
    const float* __restrict__ w_dc, const float* __restrict__ b_dc,
    float* __restrict__ out)
{
    __shared__ float s_w[8][8][9];  // [o][c][kk] for this group

    const int tid = threadIdx.x;
    const int b = blockIdx.z >> 3;
    const int g = blockIdx.z & 7;
    const int ty = tid >> 4;
    const int tx = tid & 15;
    const int h  = blockIdx.y * 16 + ty;
    const int wp = blockIdx.x * 16 + tx;

    for (int i = tid; i < 576; i += 256)
        ((float*)s_w)[i] = w_dc[(size_t)g * 576 + i];
    __syncthreads();

    const int pix = h * 128 + wp;
    const float* om_b = g_om + (size_t)b * 216 * HW;
    const float* em_b = g_em + (size_t)b * 72 * HW;
    const float* xb = x + ((size_t)b * 64 + g * 8) * HW;
    const float* sb = s + ((size_t)b * 64 + g * 8) * HW;

    float accx[8], accs[8];
#pragma unroll
    for (int o = 0; o < 8; o++) { accx[o] = 0.f; accs[o] = 0.f; }

    for (int kk = 0; kk < 9; kk++) {
        const int mch = g * 9 + kk;
        float dy   = om_b[(size_t)(2 * mch) * HW + pix];
        float dx   = om_b[(size_t)(2 * mch + 1) * HW + pix];
        float mraw = om_b[(size_t)(144 + mch) * HW + pix];
        float mx = 1.f / (1.f + expf(-mraw));
        float me = em_b[(size_t)mch * HW + pix];

        float py = (float)(h - 1 + kk / 3) + dy;
        float px = (float)(wp - 1 + kk % 3) + dx;
        float y0f = floorf(py), x0f = floorf(px);
        int y0 = (int)y0f, x0 = (int)x0f;
        float ly = py - y0f, lx = px - x0f;
        int y1 = y0 + 1, x1 = x0 + 1;

        float vy0 = (y0 >= 0 && y0 < 128) ? 1.f : 0.f;
        float vy1 = (y1 >= 0 && y1 < 128) ? 1.f : 0.f;
        float vx0 = (x0 >= 0 && x0 < 128) ? 1.f : 0.f;
        float vx1 = (x1 >= 0 && x1 < 128) ? 1.f : 0.f;

        float w00 = (1.f - ly) * (1.f - lx) * vy0 * vx0;
        float w01 = (1.f - ly) * lx         * vy0 * vx1;
        float w10 = ly * (1.f - lx)         * vy1 * vx0;
        float w11 = ly * lx                 * vy1 * vx1;

        int cy0 = min(max(y0, 0), 127), cy1 = min(max(y1, 0), 127);
        int cx0 = min(max(x0, 0), 127), cx1 = min(max(x1, 0), 127);
        int i00 = cy0 * 128 + cx0, i01 = cy0 * 128 + cx1;
        int i10 = cy1 * 128 + cx0, i11 = cy1 * 128 + cx1;

#pragma unroll
        for (int c = 0; c < 8; c++) {
            const float* xp = xb + (size_t)c * HW;
            const float* sp = sb + (size_t)c * HW;
            float vx = w00 * xp[i00] + w01 * xp[i01] + w10 * xp[i10] + w11 * xp[i11];
            float vs = w00 * sp[i00] + w01 * sp[i01] + w10 * sp[i10] + w11 * sp[i11];
            float ax  = vx * mx;
            float as_ = vs * me;
#pragma unroll
            for (int o = 0; o < 8; o++) {
                float wv = s_w[o][c][kk];
                accx[o] += ax * wv;
                accs[o] += as_ * wv;
            }
        }
    }

#pragma unroll
    for (int o = 0; o < 8; o++) {
        float bs = b_dc[g * 8 + o];
        size_t oidx = ((size_t)b * 64 + g * 8 + o) * HW + pix;
        out[oidx] = accx[o] + bs;
        out[(size_t)4 * 64 * HW + oidx] = accs[o] + bs;
    }
}

extern "C" void kernel_launch(void* const* d_in, const int* in_sizes, int n_in,
                              void* d_out, int out_size)
{
    const float* x     = (const float*)d_in[0];
    const float* shf   = (const float*)d_in[1];
    const float* off   = (const float*)d_in[2];
    const float* w_om  = (const float*)d_in[3];
    const float* b_om  = (const float*)d_in[4];
    const float* w_em1 = (const float*)d_in[5];
    const float* b_em1 = (const float*)d_in[6];
    const float* w_em2 = (const float*)d_in[7];
    const float* b_em2 = (const float*)d_in[8];
    const float* w_dc  = (const float*)d_in[9];
    const float* b_dc  = (const float*)d_in[10];
    float* out = (float*)d_out;

    float *p_om, *p_em1, *p_em;
    cudaGetSymbolAddress((void**)&p_om,  g_om);
    cudaGetSymbolAddress((void**)&p_em1, g_em1);
    cudaGetSymbolAddress((void**)&p_em,  g_em);

    // om = conv3x3(offset_feat) : 64 -> 216
    conv3x3_f2_kernel<0><<<dim3(2, 4, 4 * 27), 256>>>(
        off, nullptr, 64, 64, w_om, b_om, p_om, 216);

    // em1 = leaky(conv3x3(concat(share, offset_feat))) : 128 -> 64
    conv3x3_f2_kernel<1><<<dim3(2, 4, 4 * 8), 256>>>(
        shf, off, 64, 128, w_em1, b_em1, p_em1, 64);

    // em = sigmoid(conv3x3(em1)) : 64 -> 72
    conv3x3_f2_kernel<2><<<dim3(2, 4, 4 * 9), 256>>>(
        p_em1, nullptr, 64, 64, w_em2, b_em2, p_em, 72);

    // both deformable convs fused (shared offsets + weights)
    deform_kernel<<<dim3(8, 8, 32), 256>>>(x, shf, w_dc, b_dc, out);
}

// round 6
// speedup vs baseline: 1.3458x; 1.3458x over previous
#include <cuda_runtime.h>
#include <math.h>

#define HW 16384

// Scratch (module-load allocated, legal per harness rules)
__device__ float g_om [4 * 216 * HW];   // offset/mask conv output
__device__ float g_em1[4 *  64 * HW];   // em intermediate
__device__ float g_em [4 *  72 * HW];   // em mask (sigmoid)

// ---------------------------------------------------------------------------
// Direct 3x3 conv, stride 1, pad 1, H=W=128, NCHW fp32.
// R1-proven scalar compute (32x32 tile, 2x2 micro-tile/thread, 8 co in regs)
// + cp.async double-buffered staging so global-load latency overlaps compute.
// ACT: 0 = none, 1 = leaky(0.1), 2 = sigmoid.  Channel-concat via (in1,cin1)+in2.
// ---------------------------------------------------------------------------
template <int ACT>
__global__ __launch_bounds__(256) void conv3x3_db_kernel(
    const float* __restrict__ in1, const float* __restrict__ in2,
    int cin1, int cin,
    const float* __restrict__ wgt, const float* __restrict__ bias,
    float* __restrict__ out, int cout)
{
    __shared__ float s_in[2][4][34][36];   // 2 x 19.1 KB
    __shared__ float s_w [2][8][4][9];     // 2 x 1.1 KB

    const int tid = threadIdx.x;
    const int co_tiles = cout >> 3;
    const int b   = blockIdx.z / co_tiles;
    const int co0 = (blockIdx.z % co_tiles) << 3;
    const int h0  = blockIdx.y * 32;
    const int w0  = blockIdx.x * 32;
    const int ty  = tid >> 4;
    const int tx  = tid & 15;

    float acc[2][2][8];
#pragma unroll
    for (int sy = 0; sy < 2; sy++)
#pragma unroll
        for (int sx = 0; sx < 2; sx++)
#pragma unroll
            for (int o = 0; o < 8; o++) acc[sy][sx][o] = 0.f;

    const int nchunks = cin >> 2;

    // ---- async stage of one 4-channel chunk into buffer `buf` ----
    auto stage = [&](int cb, int buf) {
        const int c0 = cb << 2;
        // input tile: 4 x 34 x 34 (zero-padded via cp.async zfill)
#pragma unroll 5
        for (int i = tid; i < 4 * 34 * 34; i += 256) {
            int ci = i / 1156;
            int r  = i - ci * 1156;
            int yy = r / 34;
            int xx = r - yy * 34;
            int gh = h0 - 1 + yy;
            int gw = w0 - 1 + xx;
            int c  = c0 + ci;
            bool valid = (gh >= 0 && gh < 128 && gw >= 0 && gw < 128);
            int chs = min(max(gh, 0), 127);
            int cws = min(max(gw, 0), 127);
            const float* base = (c < cin1)
                ? (in1 + ((size_t)b * cin1 + c) * HW)
                : (in2 + ((size_t)b * (cin - cin1) + (c - cin1)) * HW);
            const float* src = base + chs * 128 + cws;   // always in-bounds
            unsigned sa = (unsigned)__cvta_generic_to_shared(&s_in[buf][ci][yy][xx]);
            int sz = valid ? 4 : 0;
            asm volatile("cp.async.ca.shared.global [%0], [%1], 4, %2;"
                         :: "r"(sa), "l"(src), "r"(sz));
        }
        // weights: 288 floats, layout [o][ci][k]  (grid-strided! R4 bug fix kept)
#pragma unroll
        for (int i = tid; i < 288; i += 256) {
            int o  = i / 36;
            int r  = i - o * 36;
            int ci = r / 9;
            int k  = r - ci * 9;
            const float* src = wgt + ((size_t)(co0 + o) * cin + (c0 + ci)) * 9 + k;
            unsigned sa = (unsigned)__cvta_generic_to_shared(((float*)s_w[buf]) + i);
            asm volatile("cp.async.ca.shared.global [%0], [%1], 4, 4;"
                         :: "r"(sa), "l"(src));
        }
        asm volatile("cp.async.commit_group;");
    };

    stage(0, 0);

    for (int cb = 0; cb < nchunks; cb++) {
        const int buf = cb & 1;
        if (cb + 1 < nchunks) {
            stage(cb + 1, buf ^ 1);
            asm volatile("cp.async.wait_group 1;");
        } else {
            asm volatile("cp.async.wait_group 0;");
        }
        __syncthreads();

#pragma unroll
        for (int ci = 0; ci < 4; ci++) {
#pragma unroll
            for (int ky = 0; ky < 3; ky++) {
#pragma unroll
                for (int kx = 0; kx < 3; kx++) {
                    float wv[8];
#pragma unroll
                    for (int o = 0; o < 8; o++) wv[o] = s_w[buf][o][ci][ky * 3 + kx];
#pragma unroll
                    for (int sy = 0; sy < 2; sy++) {
#pragma unroll
                        for (int sx = 0; sx < 2; sx++) {
                            float v = s_in[buf][ci][ty + 16 * sy + ky][tx + 16 * sx + kx];
#pragma unroll
                            for (int o = 0; o < 8; o++)
                                acc[sy][sx][o] += v * wv[o];
                        }
                    }
                }
            }
        }
        __syncthreads();
    }

#pragma unroll
    for (int o = 0; o < 8; o++) {
        float bs = bias[co0 + o];
#pragma unroll
        for (int sy = 0; sy < 2; sy++) {
#pragma unroll
            for (int sx = 0; sx < 2; sx++) {
                float v = acc[sy][sx][o] + bs;
                if (ACT == 1) v = (v >= 0.f) ? v : 0.1f * v;
                if (ACT == 2) v = 1.f / (1.f + expf(-v));
                out[((size_t)b * cout + co0 + o) * HW
                    + (h0 + ty + 16 * sy) * 128 + (w0 + tx + 16 * sx)] = v;
            }
        }
    }
}

// ---------------------------------------------------------------------------
// Fused dual modulated deformable conv (DCNv2), stride 1, pad 1.
// offsets/mask straight from g_om (offset = om[:, :144] verbatim):
//   dy = om[b, 2*(g*9+kk)], dx = om[b, 2*(g*9+kk)+1], mx = sigmoid(om[b,144+g*9+kk])
// second mask from g_em. Both outputs share offsets + w_dc.
// ---------------------------------------------------------------------------
__global__ __launch_bounds__(256) void deform_kernel(
    const float* __restrict__ x, const float* __restrict__ s,
    const float* __restrict__ w_dc, const float* __restrict__ b_dc,
    float* __restrict__ out)
{
    __shared__ float s_w[8][8][9];  // [o][c][kk] for this group

    const int tid = threadIdx.x;
    const int b = blockIdx.z >> 3;
    const int g = blockIdx.z & 7;
    const int ty = tid >> 4;
    const int tx = tid & 15;
    const int h  = blockIdx.y * 16 + ty;
    const int wp = blockIdx.x * 16 + tx;

    for (int i = tid; i < 576; i += 256)
        ((float*)s_w)[i] = w_dc[(size_t)g * 576 + i];
    __syncthreads();

    const int pix = h * 128 + wp;
    const float* om_b = g_om + (size_t)b * 216 * HW;
    const float* em_b = g_em + (size_t)b * 72 * HW;
    const float* xb = x + ((size_t)b * 64 + g * 8) * HW;
    const float* sb = s + ((size_t)b * 64 + g * 8) * HW;

    float accx[8], accs[8];
#pragma unroll
    for (int o = 0; o < 8; o++) { accx[o] = 0.f; accs[o] = 0.f; }

    for (int kk = 0; kk < 9; kk++) {
        const int mch = g * 9 + kk;
        float dy   = om_b[(size_t)(2 * mch) * HW + pix];
        float dx   = om_b[(size_t)(2 * mch + 1) * HW + pix];
        float mraw = om_b[(size_t)(144 + mch) * HW + pix];
        float mx = 1.f / (1.f + expf(-mraw));
        float me = em_b[(size_t)mch * HW + pix];

        float py = (float)(h - 1 + kk / 3) + dy;
        float px = (float)(wp - 1 + kk % 3) + dx;
        float y0f = floorf(py), x0f = floorf(px);
        int y0 = (int)y0f, x0 = (int)x0f;
        float ly = py - y0f, lx = px - x0f;
        int y1 = y0 + 1, x1 = x0 + 1;

        float vy0 = (y0 >= 0 && y0 < 128) ? 1.f : 0.f;
        float vy1 = (y1 >= 0 && y1 < 128) ? 1.f : 0.f;
        float vx0 = (x0 >= 0 && x0 < 128) ? 1.f : 0.f;
        float vx1 = (x1 >= 0 && x1 < 128) ? 1.f : 0.f;

        float w00 = (1.f - ly) * (1.f - lx) * vy0 * vx0;
        float w01 = (1.f - ly) * lx         * vy0 * vx1;
        float w10 = ly * (1.f - lx)         * vy1 * vx0;
        float w11 = ly * lx                 * vy1 * vx1;

        int cy0 = min(max(y0, 0), 127), cy1 = min(max(y1, 0), 127);
        int cx0 = min(max(x0, 0), 127), cx1 = min(max(x1, 0), 127);
        int i00 = cy0 * 128 + cx0, i01 = cy0 * 128 + cx1;
        int i10 = cy1 * 128 + cx0, i11 = cy1 * 128 + cx1;

#pragma unroll
        for (int c = 0; c < 8; c++) {
            const float* xp = xb + (size_t)c * HW;
            const float* sp = sb + (size_t)c * HW;
            float vx = w00 * xp[i00] + w01 * xp[i01] + w10 * xp[i10] + w11 * xp[i11];
            float vs = w00 * sp[i00] + w01 * sp[i01] + w10 * sp[i10] + w11 * sp[i11];
            float ax  = vx * mx;
            float as_ = vs * me;
#pragma unroll
            for (int o = 0; o < 8; o++) {
                float wv = s_w[o][c][kk];
                accx[o] += ax * wv;
                accs[o] += as_ * wv;
            }
        }
    }

#pragma unroll
    for (int o = 0; o < 8; o++) {
        float bs = b_dc[g * 8 + o];
        size_t oidx = ((size_t)b * 64 + g * 8 + o) * HW + pix;
        out[oidx] = accx[o] + bs;
        out[(size_t)4 * 64 * HW + oidx] = accs[o] + bs;
    }
}

extern "C" void kernel_launch(void* const* d_in, const int* in_sizes, int n_in,
                              void* d_out, int out_size)
{
    const float* x     = (const float*)d_in[0];
    const float* shf   = (const float*)d_in[1];
    const float* off   = (const float*)d_in[2];
    const float* w_om  = (const float*)d_in[3];
    const float* b_om  = (const float*)d_in[4];
    const float* w_em1 = (const float*)d_in[5];
    const float* b_em1 = (const float*)d_in[6];
    const float* w_em2 = (const float*)d_in[7];
    const float* b_em2 = (const float*)d_in[8];
    const float* w_dc  = (const float*)d_in[9];
    const float* b_dc  = (const float*)d_in[10];
    float* out = (float*)d_out;

    float *p_om, *p_em1, *p_em;
    cudaGetSymbolAddress((void**)&p_om,  g_om);
    cudaGetSymbolAddress((void**)&p_em1, g_em1);
    cudaGetSymbolAddress((void**)&p_em,  g_em);

    // om = conv3x3(offset_feat) : 64 -> 216
    conv3x3_db_kernel<0><<<dim3(4, 4, 4 * 27), 256>>>(
        off, nullptr, 64, 64, w_om, b_om, p_om, 216);

    // em1 = leaky(conv3x3(concat(share, offset_feat))) : 128 -> 64
    conv3x3_db_kernel<1><<<dim3(4, 4, 4 * 8), 256>>>(
        shf, off, 64, 128, w_em1, b_em1, p_em1, 64);

    // em = sigmoid(conv3x3(em1)) : 64 -> 72
    conv3x3_db_kernel<2><<<dim3(4, 4, 4 * 9), 256>>>(
        p_em1, nullptr, 64, 64, w_em2, b_em2, p_em, 72);

    // both deformable convs fused (shared offsets + weights)
    deform_kernel<<<dim3(8, 8, 32), 256>>>(x, shf, w_dc, b_dc, out);
}

// round 9
// speedup vs baseline: 1.4779x; 1.0981x over previous
#include <cuda_runtime.h>
#include <math.h>

#define HW 16384

// Scratch (module-load allocated, legal per harness rules)
__device__ float g_om [4 * 216 * HW];   // offset/mask conv output
__device__ float g_em1[4 *  64 * HW];   // em intermediate
__device__ float g_em [4 *  72 * HW];   // em mask (sigmoid)

// ---------------------------------------------------------------------------
// Direct 3x3 conv, stride 1, pad 1, H=W=128, NCHW fp32.
// cp.async double-buffered staging (R6-proven) + packed f32x2 compute
// (R5-proven numerics). 32x32 tile, 2x2 micro-tile/thread, 8 co as 4 f32x2
// pairs. Weights staged o-contiguous so a co-pair is one broadcast LDS.64.
// ACT: 0 = none, 1 = leaky(0.1), 2 = sigmoid.  Channel-concat via (in1,cin1)+in2.
// ---------------------------------------------------------------------------
template <int ACT>
__global__ __launch_bounds__(256) void conv3x3_db2_kernel(
    const float* __restrict__ in1, const float* __restrict__ in2,
    int cin1, int cin,
    const float* __restrict__ wgt, const float* __restrict__ bias,
    float* __restrict__ out, int cout)
{
    __shared__ float s_in[2][4][34][36];                 // 2 x 19.1 KB
    __shared__ unsigned long long s_w2[2][4][9][4];      // [buf][ci][k][co-pair]

    const int tid = threadIdx.x;
    const int co_tiles = cout >> 3;
    const int b   = blockIdx.z / co_tiles;
    const int co0 = (blockIdx.z % co_tiles) << 3;
    const int h0  = blockIdx.y * 32;
    const int w0  = blockIdx.x * 32;
    const int ty  = tid >> 4;
    const int tx  = tid & 15;

    unsigned long long acc[2][2][4];
#pragma unroll
    for (int sy = 0; sy < 2; sy++)
#pragma unroll
        for (int sx = 0; sx < 2; sx++)
#pragma unroll
            for (int p = 0; p < 4; p++) acc[sy][sx][p] = 0ull;

    const int nchunks = cin >> 2;

    // ---- async stage of one 4-channel chunk into buffer `buf` ----
    auto stage = [&](int cb, int buf) {
        const int c0 = cb << 2;
        // input tile: 4 x 34 x 34 (zero-padded via cp.async zfill)
#pragma unroll 5
        for (int i = tid; i < 4 * 34 * 34; i += 256) {
            int ci = i / 1156;
            int r  = i - ci * 1156;
            int yy = r / 34;
            int xx = r - yy * 34;
            int gh = h0 - 1 + yy;
            int gw = w0 - 1 + xx;
            int c  = c0 + ci;
            bool valid = (gh >= 0 && gh < 128 && gw >= 0 && gw < 128);
            int chs = min(max(gh, 0), 127);
            int cws = min(max(gw, 0), 127);
            const float* base = (c < cin1)
                ? (in1 + ((size_t)b * cin1 + c) * HW)
                : (in2 + ((size_t)b * (cin - cin1) + (c - cin1)) * HW);
            const float* src = base + chs * 128 + cws;   // always in-bounds
            unsigned sa = (unsigned)__cvta_generic_to_shared(&s_in[buf][ci][yy][xx]);
            int sz = valid ? 4 : 0;
            asm volatile("cp.async.ca.shared.global [%0], [%1], 4, %2;"
                         :: "r"(sa), "l"(src), "r"(sz));
        }
        // weights: 288 floats, layout [ci][k][o] with o contiguous (grid-strided)
#pragma unroll
        for (int i = tid; i < 288; i += 256) {
            int ci = i / 72;
            int r  = i - ci * 72;
            int k  = r >> 3;
            int o  = r & 7;
            const float* src = wgt + ((size_t)(co0 + o) * cin + (c0 + ci)) * 9 + k;
            unsigned sa = (unsigned)__cvta_generic_to_shared(((float*)s_w2[buf]) + i);
            asm volatile("cp.async.ca.shared.global [%0], [%1], 4, 4;"
                         :: "r"(sa), "l"(src));
        }
        asm volatile("cp.async.commit_group;");
    };

    stage(0, 0);

    for (int cb = 0; cb < nchunks; cb++) {
        const int buf = cb & 1;
        if (cb + 1 < nchunks) {
            stage(cb + 1, buf ^ 1);
            asm volatile("cp.async.wait_group 1;");
        } else {
            asm volatile("cp.async.wait_group 0;");
        }
        __syncthreads();

#pragma unroll
        for (int ci = 0; ci < 4; ci++) {
#pragma unroll
            for (int ky = 0; ky < 3; ky++) {
#pragma unroll
                for (int kx = 0; kx < 3; kx++) {
                    unsigned long long wv[4];
#pragma unroll
                    for (int p = 0; p < 4; p++)
                        wv[p] = s_w2[buf][ci][ky * 3 + kx][p];
#pragma unroll
                    for (int sy = 0; sy < 2; sy++) {
#pragma unroll
                        for (int sx = 0; sx < 2; sx++) {
                            float v = s_in[buf][ci][ty + 16 * sy + ky][tx + 16 * sx + kx];
                            unsigned long long vv;
                            asm("mov.b64 %0, {%1, %1};"
                                : "=l"(vv) : "r"(__float_as_uint(v)));
#pragma unroll
                            for (int p = 0; p < 4; p++)
                                asm("fma.rn.f32x2 %0, %1, %2, %0;"
                                    : "+l"(acc[sy][sx][p])
                                    : "l"(vv), "l"(wv[p]));
                        }
                    }
                }
            }
        }
        __syncthreads();
    }

    float bs[8];
#pragma unroll
    for (int o = 0; o < 8; o++) bs[o] = bias[co0 + o];

#pragma unroll
    for (int sy = 0; sy < 2; sy++) {
#pragma unroll
        for (int sx = 0; sx < 2; sx++) {
            int hh = h0 + ty + 16 * sy;
            int ww = w0 + tx + 16 * sx;
#pragma unroll
            for (int p = 0; p < 4; p++) {
                unsigned long long a = acc[sy][sx][p];
                float v0 = __uint_as_float((unsigned)(a & 0xffffffffu)) + bs[2 * p];
                float v1 = __uint_as_float((unsigned)(a >> 32)) + bs[2 * p + 1];
                if (ACT == 1) { v0 = (v0 >= 0.f) ? v0 : 0.1f * v0;
                                v1 = (v1 >= 0.f) ? v1 : 0.1f * v1; }
                if (ACT == 2) { v0 = 1.f / (1.f + expf(-v0));
                                v1 = 1.f / (1.f + expf(-v1)); }
                out[((size_t)b * cout + co0 + 2 * p) * HW + hh * 128 + ww] = v0;
                out[((size_t)b * cout + co0 + 2 * p + 1) * HW + hh * 128 + ww] = v1;
            }
        }
    }
}

// ---------------------------------------------------------------------------
// Fused dual modulated deformable conv (DCNv2), stride 1, pad 1.
// offsets/mask straight from g_om (offset = om[:, :144] verbatim):
//   dy = om[b, 2*(g*9+kk)], dx = om[b, 2*(g*9+kk)+1], mx = sigmoid(om[b,144+g*9+kk])
// second mask from g_em. Both outputs share offsets + w_dc.
// ---------------------------------------------------------------------------
__global__ __launch_bounds__(256) void deform_kernel(
    const float* __restrict__ x, const float* __restrict__ s,
    const float* __restrict__ w_dc, const float* __restrict__ b_dc,
    float* __restrict__ out)
{
    __shared__ float s_w[8][8][9];  // [o][c][kk] for this group

    const int tid = threadIdx.x;
    const int b = blockIdx.z >> 3;
    const int g = blockIdx.z & 7;
    const int ty = tid >> 4;
    const int tx = tid & 15;
    const int h  = blockIdx.y * 16 + ty;
    const int wp = blockIdx.x * 16 + tx;

    for (int i = tid; i < 576; i += 256)
        ((float*)s_w)[i] = w_dc[(size_t)g * 576 + i];
    __syncthreads();

    const int pix = h * 128 + wp;
    const float* om_b = g_om + (size_t)b * 216 * HW;
    const float* em_b = g_em + (size_t)b * 72 * HW;
    const float* xb = x + ((size_t)b * 64 + g * 8) * HW;
    const float* sb = s + ((size_t)b * 64 + g * 8) * HW;

    float accx[8], accs[8];
#pragma unroll
    for (int o = 0; o < 8; o++) { accx[o] = 0.f; accs[o] = 0.f; }

    for (int kk = 0; kk < 9; kk++) {
        const int mch = g * 9 + kk;
        float dy   = om_b[(size_t)(2 * mch) * HW + pix];
        float dx   = om_b[(size_t)(2 * mch + 1) * HW + pix];
        float mraw = om_b[(size_t)(144 + mch) * HW + pix];
        float mx = 1.f / (1.f + expf(-mraw));
        float me = em_b[(size_t)mch * HW + pix];

        float py = (float)(h - 1 + kk / 3) + dy;
        float px = (float)(wp - 1 + kk % 3) + dx;
        float y0f = floorf(py), x0f = floorf(px);
        int y0 = (int)y0f, x0 = (int)x0f;
        float ly = py - y0f, lx = px - x0f;
        int y1 = y0 + 1, x1 = x0 + 1;

        float vy0 = (y0 >= 0 && y0 < 128) ? 1.f : 0.f;
        float vy1 = (y1 >= 0 && y1 < 128) ? 1.f : 0.f;
        float vx0 = (x0 >= 0 && x0 < 128) ? 1.f : 0.f;
        float vx1 = (x1 >= 0 && x1 < 128) ? 1.f : 0.f;

        float w00 = (1.f - ly) * (1.f - lx) * vy0 * vx0;
        float w01 = (1.f - ly) * lx         * vy0 * vx1;
        float w10 = ly * (1.f - lx)         * vy1 * vx0;
        float w11 = ly * lx                 * vy1 * vx1;

        int cy0 = min(max(y0, 0), 127), cy1 = min(max(y1, 0), 127);
        int cx0 = min(max(x0, 0), 127), cx1 = min(max(x1, 0), 127);
        int i00 = cy0 * 128 + cx0, i01 = cy0 * 128 + cx1;
        int i10 = cy1 * 128 + cx0, i11 = cy1 * 128 + cx1;

#pragma unroll
        for (int c = 0; c < 8; c++) {
            const float* xp = xb + (size_t)c * HW;
            const float* sp = sb + (size_t)c * HW;
            float vx = w00 * xp[i00] + w01 * xp[i01] + w10 * xp[i10] + w11 * xp[i11];
            float vs = w00 * sp[i00] + w01 * sp[i01] + w10 * sp[i10] + w11 * sp[i11];
            float ax  = vx * mx;
            float as_ = vs * me;
#pragma unroll
            for (int o = 0; o < 8; o++) {
                float wv = s_w[o][c][kk];
                accx[o] += ax * wv;
                accs[o] += as_ * wv;
            }
        }
    }

#pragma unroll
    for (int o = 0; o < 8; o++) {
        float bs = b_dc[g * 8 + o];
        size_t oidx = ((size_t)b * 64 + g * 8 + o) * HW + pix;
        out[oidx] = accx[o] + bs;
        out[(size_t)4 * 64 * HW + oidx] = accs[o] + bs;
    }
}

extern "C" void kernel_launch(void* const* d_in, const int* in_sizes, int n_in,
                              void* d_out, int out_size)
{
    const float* x     = (const float*)d_in[0];
    const float* shf   = (const float*)d_in[1];
    const float* off   = (const float*)d_in[2];
    const float* w_om  = (const float*)d_in[3];
    const float* b_om  = (const float*)d_in[4];
    const float* w_em1 = (const float*)d_in[5];
    const float* b_em1 = (const float*)d_in[6];
    const float* w_em2 = (const float*)d_in[7];
    const float* b_em2 = (const float*)d_in[8];
    const float* w_dc  = (const float*)d_in[9];
    const float* b_dc  = (const float*)d_in[10];
    float* out = (float*)d_out;

    float *p_om, *p_em1, *p_em;
    cudaGetSymbolAddress((void**)&p_om,  g_om);
    cudaGetSymbolAddress((void**)&p_em1, g_em1);
    cudaGetSymbolAddress((void**)&p_em,  g_em);

    // om = conv3x3(offset_feat) : 64 -> 216
    conv3x3_db2_kernel<0><<<dim3(4, 4, 4 * 27), 256>>>(
        off, nullptr, 64, 64, w_om, b_om, p_om, 216);

    // em1 = leaky(conv3x3(concat(share, offset_feat))) : 128 -> 64
    conv3x3_db2_kernel<1><<<dim3(4, 4, 4 * 8), 256>>>(
        shf, off, 64, 128, w_em1, b_em1, p_em1, 64);

    // em = sigmoid(conv3x3(em1)) : 64 -> 72
    conv3x3_db2_kernel<2><<<dim3(4, 4, 4 * 9), 256>>>(
        p_em1, nullptr, 64, 64, w_em2, b_em2, p_em, 72);

    // both deformable convs fused (shared offsets + weights)
    deform_kernel<<<dim3(8, 8, 32), 256>>>(x, shf, w_dc, b_dc, out);
}

// round 10
// speedup vs baseline: 1.5455x; 1.0457x over previous
#include <cuda_runtime.h>
#include <math.h>

#define HW 16384

// Scratch (module-load allocated, legal per harness rules)
__device__ float g_om [4 * 216 * HW];   // offset/mask conv output
__device__ float g_em1[4 *  64 * HW];   // em intermediate
__device__ float g_em [4 *  72 * HW];   // em mask (sigmoid)

// ---------------------------------------------------------------------------
// Direct 3x3 conv, stride 1, pad 1, H=W=128, NCHW fp32.
// 64(w) x 32(h) tile, 8 px/thread (R5-proven geometry) + cp.async
// double-buffered staging (R6/R9-proven) + packed f32x2 compute.
// Weights staged o-contiguous so a co-pair is one broadcast LDS.64.
// ACT: 0 = none, 1 = leaky(0.1), 2 = sigmoid.  Channel-concat via (in1,cin1)+in2.
// ---------------------------------------------------------------------------
template <int ACT>
__global__ __launch_bounds__(256, 2) void conv3x3_w64_kernel(
    const float* __restrict__ in1, const float* __restrict__ in2,
    int cin1, int cin,
    const float* __restrict__ wgt, const float* __restrict__ bias,
    float* __restrict__ out, int cout)
{
    __shared__ float s_in[2][4][34][66];                 // 2 x 35.9 KB
    __shared__ unsigned long long s_w2[2][4][9][4];      // [buf][ci][k][co-pair]

    const int tid = threadIdx.x;
    const int co_tiles = cout >> 3;
    const int b   = blockIdx.z / co_tiles;
    const int co0 = (blockIdx.z % co_tiles) << 3;
    const int h0  = blockIdx.y * 32;
    const int w0  = blockIdx.x * 64;
    const int tx  = tid & 31;
    const int ty  = tid >> 5;     // 0..7

    unsigned long long acc[8][4];
#pragma unroll
    for (int i = 0; i < 8; i++)
#pragma unroll
        for (int p = 0; p < 4; p++) acc[i][p] = 0ull;

    const int nchunks = cin >> 2;

    // ---- async stage of one 4-channel chunk into buffer `buf` ----
    auto stage = [&](int cb, int buf) {
        const int c0 = cb << 2;
        // input tile: 4 x 34 x 66 (zero-padded via cp.async zfill)
        for (int i = tid; i < 4 * 34 * 66; i += 256) {
            int ci = i / 2244;
            int r  = i - ci * 2244;
            int yy = r / 66;
            int xx = r - yy * 66;
            int gh = h0 - 1 + yy;
            int gw = w0 - 1 + xx;
            int c  = c0 + ci;
            bool valid = (gh >= 0 && gh < 128 && gw >= 0 && gw < 128);
            int chs = min(max(gh, 0), 127);
            int cws = min(max(gw, 0), 127);
            const float* base = (c < cin1)
                ? (in1 + ((size_t)b * cin1 + c) * HW)
                : (in2 + ((size_t)b * (cin - cin1) + (c - cin1)) * HW);
            const float* src = base + chs * 128 + cws;   // always in-bounds
            unsigned sa = (unsigned)__cvta_generic_to_shared(&s_in[buf][ci][yy][xx]);
            int sz = valid ? 4 : 0;
            asm volatile("cp.async.ca.shared.global [%0], [%1], 4, %2;"
                         :: "r"(sa), "l"(src), "r"(sz));
        }
        // weights: 288 floats, layout [ci][k][o] with o contiguous (grid-strided)
#pragma unroll
        for (int i = tid; i < 288; i += 256) {
            int ci = i / 72;
            int r  = i - ci * 72;
            int k  = r >> 3;
            int o  = r & 7;
            const float* src = wgt + ((size_t)(co0 + o) * cin + (c0 + ci)) * 9 + k;
            unsigned sa = (unsigned)__cvta_generic_to_shared(((float*)s_w2[buf]) + i);
            asm volatile("cp.async.ca.shared.global [%0], [%1], 4, 4;"
                         :: "r"(sa), "l"(src));
        }
        asm volatile("cp.async.commit_group;");
    };

    stage(0, 0);

    for (int cb = 0; cb < nchunks; cb++) {
        const int buf = cb & 1;
        if (cb + 1 < nchunks) {
            stage(cb + 1, buf ^ 1);
            asm volatile("cp.async.wait_group 1;");
        } else {
            asm volatile("cp.async.wait_group 0;");
        }
        __syncthreads();

#pragma unroll 1
        for (int ci = 0; ci < 4; ci++) {
#pragma unroll
            for (int ky = 0; ky < 3; ky++) {
#pragma unroll
                for (int kx = 0; kx < 3; kx++) {
                    unsigned long long wv[4];
#pragma unroll
                    for (int p = 0; p < 4; p++)
                        wv[p] = s_w2[buf][ci][ky * 3 + kx][p];
#pragma unroll
                    for (int sy = 0; sy < 4; sy++) {
#pragma unroll
                        for (int sx = 0; sx < 2; sx++) {
                            float v = s_in[buf][ci][ty + 8 * sy + ky][tx + 32 * sx + kx];
                            unsigned long long vv;
                            asm("mov.b64 %0, {%1, %1};"
                                : "=l"(vv) : "r"(__float_as_uint(v)));
#pragma unroll
                            for (int p = 0; p < 4; p++)
                                asm("fma.rn.f32x2 %0, %1, %2, %0;"
                                    : "+l"(acc[sy * 2 + sx][p])
                                    : "l"(vv), "l"(wv[p]));
                        }
                    }
                }
            }
        }
        __syncthreads();
    }

    float bs[8];
#pragma unroll
    for (int o = 0; o < 8; o++) bs[o] = bias[co0 + o];

#pragma unroll
    for (int sy = 0; sy < 4; sy++) {
#pragma unroll
        for (int sx = 0; sx < 2; sx++) {
            int hh = h0 + ty + 8 * sy;
            int ww = w0 + tx + 32 * sx;
#pragma unroll
            for (int p = 0; p < 4; p++) {
                unsigned long long a = acc[sy * 2 + sx][p];
                float v0 = __uint_as_float((unsigned)(a & 0xffffffffu)) + bs[2 * p];
                float v1 = __uint_as_float((unsigned)(a >> 32)) + bs[2 * p + 1];
                if (ACT == 1) { v0 = (v0 >= 0.f) ? v0 : 0.1f * v0;
                                v1 = (v1 >= 0.f) ? v1 : 0.1f * v1; }
                if (ACT == 2) { v0 = 1.f / (1.f + expf(-v0));
                                v1 = 1.f / (1.f + expf(-v1)); }
                out[((size_t)b * cout + co0 + 2 * p) * HW + hh * 128 + ww] = v0;
                out[((size_t)b * cout + co0 + 2 * p + 1) * HW + hh * 128 + ww] = v1;
            }
        }
    }
}

// ---------------------------------------------------------------------------
// Fused dual modulated deformable conv (DCNv2), stride 1, pad 1.
// offsets/mask straight from g_om (offset = om[:, :144] verbatim):
//   dy = om[b, 2*(g*9+kk)], dx = om[b, 2*(g*9+kk)+1], mx = sigmoid(om[b,144+g*9+kk])
// second mask from g_em. Both outputs share offsets + w_dc.
// ---------------------------------------------------------------------------
__global__ __launch_bounds__(256) void deform_kernel(
    const float* __restrict__ x, const float* __restrict__ s,
    const float* __restrict__ w_dc, const float* __restrict__ b_dc,
    float* __restrict__ out)
{
    __shared__ float s_w[8][8][9];  // [o][c][kk] for this group

    const int tid = threadIdx.x;
    const int b = blockIdx.z >> 3;
    const int g = blockIdx.z & 7;
    const int ty = tid >> 4;
    const int tx = tid & 15;
    const int h  = blockIdx.y * 16 + ty;
    const int wp = blockIdx.x * 16 + tx;

    for (int i = tid; i < 576; i += 256)
        ((float*)s_w)[i] = w_dc[(size_t)g * 576 + i];
    __syncthreads();

    const int pix = h * 128 + wp;
    const float* om_b = g_om + (size_t)b * 216 * HW;
    const float* em_b = g_em + (size_t)b * 72 * HW;
    const float* xb = x + ((size_t)b * 64 + g * 8) * HW;
    const float* sb = s + ((size_t)b * 64 + g * 8) * HW;

    float accx[8], accs[8];
#pragma unroll
    for (int o = 0; o < 8; o++) { accx[o] = 0.f; accs[o] = 0.f; }

    for (int kk = 0; kk < 9; kk++) {
        const int mch = g * 9 + kk;
        float dy   = om_b[(size_t)(2 * mch) * HW + pix];
        float dx   = om_b[(size_t)(2 * mch + 1) * HW + pix];
        float mraw = om_b[(size_t)(144 + mch) * HW + pix];
        float mx = 1.f / (1.f + expf(-mraw));
        float me = em_b[(size_t)mch * HW + pix];

        float py = (float)(h - 1 + kk / 3) + dy;
        float px = (float)(wp - 1 + kk % 3) + dx;
        float y0f = floorf(py), x0f = floorf(px);
        int y0 = (int)y0f, x0 = (int)x0f;
        float ly = py - y0f, lx = px - x0f;
        int y1 = y0 + 1, x1 = x0 + 1;

        float vy0 = (y0 >= 0 && y0 < 128) ? 1.f : 0.f;
        float vy1 = (y1 >= 0 && y1 < 128) ? 1.f : 0.f;
        float vx0 = (x0 >= 0 && x0 < 128) ? 1.f : 0.f;
        float vx1 = (x1 >= 0 && x1 < 128) ? 1.f : 0.f;

        float w00 = (1.f - ly) * (1.f - lx) * vy0 * vx0;
        float w01 = (1.f - ly) * lx         * vy0 * vx1;
        float w10 = ly * (1.f - lx)         * vy1 * vx0;
        float w11 = ly * lx                 * vy1 * vx1;

        int cy0 = min(max(y0, 0), 127), cy1 = min(max(y1, 0), 127);
        int cx0 = min(max(x0, 0), 127), cx1 = min(max(x1, 0), 127);
        int i00 = cy0 * 128 + cx0, i01 = cy0 * 128 + cx1;
        int i10 = cy1 * 128 + cx0, i11 = cy1 * 128 + cx1;

#pragma unroll
        for (int c = 0; c < 8; c++) {
            const float* xp = xb + (size_t)c * HW;
            const float* sp = sb + (size_t)c * HW;
            float vx = w00 * xp[i00] + w01 * xp[i01] + w10 * xp[i10] + w11 * xp[i11];
            float vs = w00 * sp[i00] + w01 * sp[i01] + w10 * sp[i10] + w11 * sp[i11];
            float ax  = vx * mx;
            float as_ = vs * me;
#pragma unroll
            for (int o = 0; o < 8; o++) {
                float wv = s_w[o][c][kk];
                accx[o] += ax * wv;
                accs[o] += as_ * wv;
            }
        }
    }

#pragma unroll
    for (int o = 0; o < 8; o++) {
        float bs = b_dc[g * 8 + o];
        size_t oidx = ((size_t)b * 64 + g * 8 + o) * HW + pix;
        out[oidx] = accx[o] + bs;
        out[(size_t)4 * 64 * HW + oidx] = accs[o] + bs;
    }
}

extern "C" void kernel_launch(void* const* d_in, const int* in_sizes, int n_in,
                              void* d_out, int out_size)
{
    const float* x     = (const float*)d_in[0];
    const float* shf   = (const float*)d_in[1];
    const float* off   = (const float*)d_in[2];
    const float* w_om  = (const float*)d_in[3];
    const float* b_om  = (const float*)d_in[4];
    const float* w_em1 = (const float*)d_in[5];
    const float* b_em1 = (const float*)d_in[6];
    const float* w_em2 = (const float*)d_in[7];
    const float* b_em2 = (const float*)d_in[8];
    const float* w_dc  = (const float*)d_in[9];
    const float* b_dc  = (const float*)d_in[10];
    float* out = (float*)d_out;

    float *p_om, *p_em1, *p_em;
    cudaGetSymbolAddress((void**)&p_om,  g_om);
    cudaGetSymbolAddress((void**)&p_em1, g_em1);
    cudaGetSymbolAddress((void**)&p_em,  g_em);

    // om = conv3x3(offset_feat) : 64 -> 216
    conv3x3_w64_kernel<0><<<dim3(2, 4, 4 * 27), 256>>>(
        off, nullptr, 64, 64, w_om, b_om, p_om, 216);

    // em1 = leaky(conv3x3(concat(share, offset_feat))) : 128 -> 64
    conv3x3_w64_kernel<1><<<dim3(2, 4, 4 * 8), 256>>>(
        shf, off, 64, 128, w_em1, b_em1, p_em1, 64);

    // em = sigmoid(conv3x3(em1)) : 64 -> 72
    conv3x3_w64_kernel<2><<<dim3(2, 4, 4 * 9), 256>>>(
        p_em1, nullptr, 64, 64, w_em2, b_em2, p_em, 72);

    // both deformable convs fused (shared offsets + weights)
    deform_kernel<<<dim3(8, 8, 32), 256>>>(x, shf, w_dc, b_dc, out);
}

// round 12
// speedup vs baseline: 2.1493x; 1.3907x over previous
#include <cuda_runtime.h>
#include <cuda_bf16.h>
#include <math.h>
#include <stdint.h>

#define HW 16384

// Scratch (module-load allocated, legal per harness rules)
__device__ float g_om [4 * 216 * HW];   // offset/mask conv output
__device__ float g_em1[4 *  64 * HW];   // em intermediate
__device__ float g_em [4 *  72 * HW];   // em mask (sigmoid)

// Pre-split weights: packed (bf16 hi | bf16 lo << 16), K-major [Co][Cin*9]
__device__ uint32_t g_w_om [216 *  576];
__device__ uint32_t g_w_em1[ 64 * 1152];
__device__ uint32_t g_w_em2[ 72 *  576];

// ---------------------------------------------------------------------------
// fp32 -> (bf16 hi, bf16 lo) split, packed into uint32. Elementwise.
// ---------------------------------------------------------------------------
__global__ void wsplit_kernel(const float* __restrict__ w,
                              uint32_t* __restrict__ dst, int n)
{
    int i = blockIdx.x * 256 + threadIdx.x;
    if (i >= n) return;
    float x = w[i];
    __nv_bfloat16 h = __float2bfloat16(x);
    float r = x - __bfloat162float(h);
    __nv_bfloat16 l = __float2bfloat16(r);
    dst[i] = (uint32_t)__bfloat16_as_ushort(h)
           | ((uint32_t)__bfloat16_as_ushort(l) << 16);
}

// ---------------------------------------------------------------------------
// warp-mma helpers (baseline PTX: valid at compute_103, no tcgen05 needed)
// ---------------------------------------------------------------------------
__device__ __forceinline__ void ldm_x4(uint32_t* r, uint32_t addr) {
    asm volatile("ldmatrix.sync.aligned.m8n8.x4.shared.b16 {%0,%1,%2,%3}, [%4];"
        : "=r"(r[0]), "=r"(r[1]), "=r"(r[2]), "=r"(r[3]) : "r"(addr));
}
__device__ __forceinline__ void ldm_x2(uint32_t* r, uint32_t addr) {
    asm volatile("ldmatrix.sync.aligned.m8n8.x2.shared.b16 {%0,%1}, [%2];"
        : "=r"(r[0]), "=r"(r[1]) : "r"(addr));
}
__device__ __forceinline__ void mma_bf16(float* c, const uint32_t* a, const uint32_t* b) {
    asm volatile("mma.sync.aligned.m16n8k16.row.col.f32.bf16.bf16.f32 "
        "{%0,%1,%2,%3},{%4,%5,%6,%7},{%8,%9},{%0,%1,%2,%3};"
        : "+f"(c[0]), "+f"(c[1]), "+f"(c[2]), "+f"(c[3])
        : "r"(a[0]), "r"(a[1]), "r"(a[2]), "r"(a[3]), "r"(b[0]), "r"(b[1]));
}

// ---------------------------------------------------------------------------
// Implicit-GEMM 3x3 conv (stride1 pad1, H=W=128, NCHW fp32 in/out) on
// mma.sync bf16 tensor cores with hi/lo 3-pass split (fp32-grade accuracy).
// Per block: M = 128 pixels (image row h), N = COUT_T (blockIdx.z tile),
// K = CIN*9 chunked by 64. smem rows padded to 144B: every ldmatrix access
// is bank = lane (conflict-free).
// ACT: 0 none, 1 leaky(0.1), 2 sigmoid. Channel concat via (in1,CIN1)+in2.
// ---------------------------------------------------------------------------
template<int CIN, int CIN1, int COUT_T, int COUT_TOT, int ACT>
__global__ __launch_bounds__(256, 2) void conv_mma_kernel(
    const float* __restrict__ in1, const float* __restrict__ in2,
    const uint32_t* __restrict__ wsp,
    const float* __restrict__ bias, float* __restrict__ out)
{
    constexpr int K    = CIN * 9;
    constexpr int NCH  = K / 64;           // 9 or 18
    constexpr int NT8  = COUT_T / 8;
    constexpr int AW   = 36;               // words per padded row (144 B)
    constexpr int ALO  = 128 * 144;        // byte offsets in dynamic smem
    constexpr int BHI  = 2 * ALO;
    constexpr int BLO  = BHI + COUT_T * 144;

    extern __shared__ char smem[];
    uint32_t sb;
    asm("{ .reg .u64 t; cvta.to.shared.u64 t, %1; cvt.u32.u64 %0, t; }"
        : "=r"(sb) : "l"(smem));
    uint32_t* sw = (uint32_t*)smem;

    const int tid  = threadIdx.x;
    const int lane = tid & 31;
    const int wid  = tid >> 5;
    const int h    = blockIdx.x;
    const int b    = blockIdx.y;
    const int co0  = blockIdx.z * COUT_T;

    float acc[NT8][4];
#pragma unroll
    for (int nt = 0; nt < NT8; nt++)
#pragma unroll
        for (int q = 0; q < 4; q++) acc[nt][q] = 0.f;

    // ldmatrix lane addresses (fixed per thread)
    const int m0 = wid * 16;
    const uint32_t a_row = (uint32_t)(m0 + ((lane >> 3) & 1) * 8 + (lane & 7));
    const uint32_t a_cw  = (uint32_t)((lane >> 4) * 4);
    const uint32_t aaddr = sb + (a_row * AW + a_cw) * 4;
    const uint32_t b_row = (uint32_t)(lane & 7);
    const uint32_t b_cw  = (uint32_t)(((lane >> 3) & 1) * 4);
    const uint32_t baddr = sb + BHI + (b_row * AW + b_cw) * 4;

    const int jp = lane;        // k-pair index within chunk (0..31)
    const int mb = wid;         // m stride base (0..7)

    for (int kc = 0; kc < NCH; kc++) {
        // ---- stage A: im2col + bf16 split, pair-packed STS.32 ----
        {
            int k0 = kc * 64 + 2 * jp, k1 = k0 + 1;
            int ci0 = k0 / 9, r0 = k0 - 9 * ci0, ky0 = r0 / 3, kx0 = r0 - 3 * ky0;
            int ci1 = k1 / 9, r1 = k1 - 9 * ci1, ky1 = r1 / 3, kx1 = r1 - 3 * ky1;
            int gh0 = h - 1 + ky0, gh1 = h - 1 + ky1;
            bool ok0 = (gh0 >= 0) && (gh0 < 128);
            bool ok1 = (gh1 >= 0) && (gh1 < 128);
            const float* p0 = ((ci0 < CIN1)
                ? in1 + ((size_t)b * CIN1 + ci0) * HW
                : in2 + ((size_t)b * (CIN - CIN1) + ci0 - CIN1) * HW) + gh0 * 128;
            const float* p1 = ((ci1 < CIN1)
                ? in1 + ((size_t)b * CIN1 + ci1) * HW
                : in2 + ((size_t)b * (CIN - CIN1) + ci1 - CIN1) * HW) + gh1 * 128;
#pragma unroll
            for (int mi = 0; mi < 16; mi++) {
                int m  = mb + 8 * mi;
                int g0 = m - 1 + kx0, g1 = m - 1 + kx1;
                float v0 = (ok0 && g0 >= 0 && g0 < 128) ? p0[g0] : 0.f;
                float v1 = (ok1 && g1 >= 0 && g1 < 128) ? p1[g1] : 0.f;
                __nv_bfloat16 h0 = __float2bfloat16(v0);
                __nv_bfloat16 h1 = __float2bfloat16(v1);
                __nv_bfloat16 l0 = __float2bfloat16(v0 - __bfloat162float(h0));
                __nv_bfloat16 l1 = __float2bfloat16(v1 - __bfloat162float(h1));
                uint32_t hp = (uint32_t)__bfloat16_as_ushort(h0)
                            | ((uint32_t)__bfloat16_as_ushort(h1) << 16);
                uint32_t lp = (uint32_t)__bfloat16_as_ushort(l0)
                            | ((uint32_t)__bfloat16_as_ushort(l1) << 16);
                sw[m * AW + jp]             = hp;
                sw[(ALO >> 2) + m * AW + jp] = lp;
            }
        }
        // ---- stage B: unpack pre-split weights, pair-packed ----
        for (int idx = tid; idx < COUT_T * 32; idx += 256) {
            int co = idx >> 5, kp = idx & 31;
            const uint32_t* wp = wsp + (size_t)(co0 + co) * K + kc * 64 + 2 * kp;
            uint32_t e0 = wp[0], e1 = wp[1];
            sw[(BHI >> 2) + co * AW + kp] = (e0 & 0xFFFFu) | (e1 << 16);
            sw[(BLO >> 2) + co * AW + kp] = (e0 >> 16) | (e1 & 0xFFFF0000u);
        }
        __syncthreads();

        // ---- tensor-core mainloop: 3-pass split ----
#pragma unroll
        for (int kt = 0; kt < 4; kt++) {
            uint32_t ah[4], al[4];
            ldm_x4(ah, aaddr + kt * 32);
            ldm_x4(al, aaddr + ALO + kt * 32);
#pragma unroll
            for (int nt = 0; nt < NT8; nt++) {
                uint32_t bh[2], bl[2];
                ldm_x2(bh, baddr + nt * 1152 + kt * 32);
                ldm_x2(bl, baddr + (BLO - BHI) + nt * 1152 + kt * 32);
                mma_bf16(acc[nt], ah, bh);
                mma_bf16(acc[nt], ah, bl);
                mma_bf16(acc[nt], al, bh);
            }
        }
        __syncthreads();
    }

    // ---- epilogue: fragment regs -> bias/act -> NCHW stores ----
    const int mA = m0 + (lane >> 2);
#pragma unroll
    for (int nt = 0; nt < NT8; nt++) {
        int coA = co0 + nt * 8 + 2 * (lane & 3);
        float ba = bias[coA], bb = bias[coA + 1];
        float v[4] = { acc[nt][0] + ba, acc[nt][1] + bb,
                       acc[nt][2] + ba, acc[nt][3] + bb };
#pragma unroll
        for (int q = 0; q < 4; q++) {
            if (ACT == 1) v[q] = (v[q] >= 0.f) ? v[q] : 0.1f * v[q];
            if (ACT == 2) v[q] = 1.f / (1.f + expf(-v[q]));
        }
        size_t o00 = ((size_t)b * COUT_TOT + coA) * HW + h * 128 + mA;
        size_t o01 = o00 + HW;               // coA+1
        out[o00]     = v[0];
        out[o01]     = v[1];
        out[o00 + 8] = v[2];                 // mA+8
        out[o01 + 8] = v[3];
    }
}

// ---------------------------------------------------------------------------
// Fused dual modulated deformable conv (DCNv2), stride 1, pad 1. (unchanged)
// ---------------------------------------------------------------------------
__global__ __launch_bounds__(256) void deform_kernel(
    const float* __restrict__ x, const float* __restrict__ s,
    const float* __restrict__ w_dc, const float* __restrict__ b_dc,
    float* __restrict__ out)
{
    __shared__ float s_w[8][8][9];  // [o][c][kk] for this group

    const int tid = threadIdx.x;
    const int b = blockIdx.z >> 3;
    const int g = blockIdx.z & 7;
    const int ty = tid >> 4;
    const int tx = tid & 15;
    const int h  = blockIdx.y * 16 + ty;
    const int wp = blockIdx.x * 16 + tx;

    for (int i = tid; i < 576; i += 256)
        ((float*)s_w)[i] = w_dc[(size_t)g * 576 + i];
    __syncthreads();

    const int pix = h * 128 + wp;
    const float* om_b = g_om + (size_t)b * 216 * HW;
    const float* em_b = g_em + (size_t)b * 72 * HW;
    const float* xb = x + ((size_t)b * 64 + g * 8) * HW;
    const float* sb = s + ((size_t)b * 64 + g * 8) * HW;

    float accx[8], accs[8];
#pragma unroll
    for (int o = 0; o < 8; o++) { accx[o] = 0.f; accs[o] = 0.f; }

    for (int kk = 0; kk < 9; kk++) {
        const int mch = g * 9 + kk;
        float dy   = om_b[(size_t)(2 * mch) * HW + pix];
        float dx   = om_b[(size_t)(2 * mch + 1) * HW + pix];
        float mraw = om_b[(size_t)(144 + mch) * HW + pix];
        float mx = 1.f / (1.f + expf(-mraw));
        float me = em_b[(size_t)mch * HW + pix];

        float py = (float)(h - 1 + kk / 3) + dy;
        float px = (float)(wp - 1 + kk % 3) + dx;
        float y0f = floorf(py), x0f = floorf(px);
        int y0 = (int)y0f, x0 = (int)x0f;
        float ly = py - y0f, lx = px - x0f;
        int y1 = y0 + 1, x1 = x0 + 1;

        float vy0 = (y0 >= 0 && y0 < 128) ? 1.f : 0.f;
        float vy1 = (y1 >= 0 && y1 < 128) ? 1.f : 0.f;
        float vx0 = (x0 >= 0 && x0 < 128) ? 1.f : 0.f;
        float vx1 = (x1 >= 0 && x1 < 128) ? 1.f : 0.f;

        float w00 = (1.f - ly) * (1.f - lx) * vy0 * vx0;
        float w01 = (1.f - ly) * lx         * vy0 * vx1;
        float w10 = ly * (1.f - lx)         * vy1 * vx0;
        float w11 = ly * lx                 * vy1 * vx1;

        int cy0 = min(max(y0, 0), 127), cy1 = min(max(y1, 0), 127);
        int cx0 = min(max(x0, 0), 127), cx1 = min(max(x1, 0), 127);
        int i00 = cy0 * 128 + cx0, i01 = cy0 * 128 + cx1;
        int i10 = cy1 * 128 + cx0, i11 = cy1 * 128 + cx1;

#pragma unroll
        for (int c = 0; c < 8; c++) {
            const float* xp = xb + (size_t)c * HW;
            const float* sp = sb + (size_t)c * HW;
            float vx = w00 * xp[i00] + w01 * xp[i01] + w10 * xp[i10] + w11 * xp[i11];
            float vs = w00 * sp[i00] + w01 * sp[i01] + w10 * sp[i10] + w11 * sp[i11];
            float ax  = vx * mx;
            float as_ = vs * me;
#pragma unroll
            for (int o = 0; o < 8; o++) {
                float wv = s_w[o][c][kk];
                accx[o] += ax * wv;
                accs[o] += as_ * wv;
            }
        }
    }

#pragma unroll
    for (int o = 0; o < 8; o++) {
        float bs = b_dc[g * 8 + o];
        size_t oidx = ((size_t)b * 64 + g * 8 + o) * HW + pix;
        out[oidx] = accx[o] + bs;
        out[(size_t)4 * 64 * HW + oidx] = accs[o] + bs;
    }
}

extern "C" void kernel_launch(void* const* d_in, const int* in_sizes, int n_in,
                              void* d_out, int out_size)
{
    const float* x     = (const float*)d_in[0];
    const float* shf   = (const float*)d_in[1];
    const float* off   = (const float*)d_in[2];
    const float* w_om  = (const float*)d_in[3];
    const float* b_om  = (const float*)d_in[4];
    const float* w_em1 = (const float*)d_in[5];
    const float* b_em1 = (const float*)d_in[6];
    const float* w_em2 = (const float*)d_in[7];
    const float* b_em2 = (const float*)d_in[8];
    const float* w_dc  = (const float*)d_in[9];
    const float* b_dc  = (const float*)d_in[10];
    float* out = (float*)d_out;

    float *p_om, *p_em1, *p_em;
    uint32_t *pw_om, *pw_em1, *pw_em2;
    cudaGetSymbolAddress((void**)&p_om,  g_om);
    cudaGetSymbolAddress((void**)&p_em1, g_em1);
    cudaGetSymbolAddress((void**)&p_em,  g_em);
    cudaGetSymbolAddress((void**)&pw_om,  g_w_om);
    cudaGetSymbolAddress((void**)&pw_em1, g_w_em1);
    cudaGetSymbolAddress((void**)&pw_em2, g_w_em2);

    // dynamic smem: 36864 + 2*COUT_T*144
    const int SM_72 = 36864 + 2 * 72 * 144;   // 57600
    const int SM_64 = 36864 + 2 * 64 * 144;   // 55296
    cudaFuncSetAttribute(conv_mma_kernel<64, 64, 72, 216, 0>,
                         cudaFuncAttributeMaxDynamicSharedMemorySize, SM_72);
    cudaFuncSetAttribute(conv_mma_kernel<128, 64, 64, 64, 1>,
                         cudaFuncAttributeMaxDynamicSharedMemorySize, SM_64);
    cudaFuncSetAttribute(conv_mma_kernel<64, 64, 72, 72, 2>,
                         cudaFuncAttributeMaxDynamicSharedMemorySize, SM_72);

    // split weights into bf16 (hi,lo) pairs
    wsplit_kernel<<<(216 *  576 + 255) / 256, 256>>>(w_om,  pw_om,  216 *  576);
    wsplit_kernel<<<( 64 * 1152 + 255) / 256, 256>>>(w_em1, pw_em1,  64 * 1152);
    wsplit_kernel<<<( 72 *  576 + 255) / 256, 256>>>(w_em2, pw_em2,  72 *  576);

    // om = conv3x3(offset_feat) : 64 -> 216
    conv_mma_kernel<64, 64, 72, 216, 0><<<dim3(128, 4, 3), 256, SM_72>>>(
        off, off, pw_om, b_om, p_om);

    // em1 = leaky(conv3x3(concat(share, offset_feat))) : 128 -> 64
    conv_mma_kernel<128, 64, 64, 64, 1><<<dim3(128, 4, 1), 256, SM_64>>>(
        shf, off, pw_em1, b_em1, p_em1);

    // em = sigmoid(conv3x3(em1)) : 64 -> 72
    conv_mma_kernel<64, 64, 72, 72, 2><<<dim3(128, 4, 1), 256, SM_72>>>(
        p_em1, p_em1, pw_em2, b_em2, p_em);

    // both deformable convs fused (shared offsets + weights)
    deform_kernel<<<dim3(8, 8, 32), 256>>>(x, shf, w_dc, b_dc, out);
}

// round 13
// speedup vs baseline: 2.3541x; 1.0953x over previous
#include <cuda_runtime.h>
#include <cuda_bf16.h>
#include <math.h>
#include <stdint.h>

#define HW 16384

// Scratch (module-load allocated, legal per harness rules)
__device__ float g_om [4 * 216 * HW];   // offset/mask conv output
__device__ float g_em1[4 *  64 * HW];   // em intermediate
__device__ float g_em [4 *  72 * HW];   // em mask (sigmoid)

// Pre-split weights: packed (bf16 hi | bf16 lo << 16), K-major [Co][Cin*9]
__device__ uint32_t g_w_om [216 *  576];
__device__ uint32_t g_w_em1[ 64 * 1152];
__device__ uint32_t g_w_em2[ 72 *  576];

// ---------------------------------------------------------------------------
// fp32 -> (bf16 hi, bf16 lo) split, packed into uint32. Elementwise.
// ---------------------------------------------------------------------------
__global__ void wsplit_kernel(const float* __restrict__ w,
                              uint32_t* __restrict__ dst, int n)
{
    int i = blockIdx.x * 256 + threadIdx.x;
    if (i >= n) return;
    float x = w[i];
    __nv_bfloat16 h = __float2bfloat16(x);
    float r = x - __bfloat162float(h);
    __nv_bfloat16 l = __float2bfloat16(r);
    dst[i] = (uint32_t)__bfloat16_as_ushort(h)
           | ((uint32_t)__bfloat16_as_ushort(l) << 16);
}

// ---------------------------------------------------------------------------
// warp-mma helpers (baseline PTX: valid at compute_103, no tcgen05 needed)
// ---------------------------------------------------------------------------
__device__ __forceinline__ void ldm_x4(uint32_t* r, uint32_t addr) {
    asm volatile("ldmatrix.sync.aligned.m8n8.x4.shared.b16 {%0,%1,%2,%3}, [%4];"
        : "=r"(r[0]), "=r"(r[1]), "=r"(r[2]), "=r"(r[3]) : "r"(addr));
}
__device__ __forceinline__ void ldm_x2(uint32_t* r, uint32_t addr) {
    asm volatile("ldmatrix.sync.aligned.m8n8.x2.shared.b16 {%0,%1}, [%2];"
        : "=r"(r[0]), "=r"(r[1]) : "r"(addr));
}
__device__ __forceinline__ void mma_bf16(float* c, const uint32_t* a, const uint32_t* b) {
    asm volatile("mma.sync.aligned.m16n8k16.row.col.f32.bf16.bf16.f32 "
        "{%0,%1,%2,%3},{%4,%5,%6,%7},{%8,%9},{%0,%1,%2,%3};"
        : "+f"(c[0]), "+f"(c[1]), "+f"(c[2]), "+f"(c[3])
        : "r"(a[0]), "r"(a[1]), "r"(a[2]), "r"(a[3]), "r"(b[0]), "r"(b[1]));
}

// ===========================================================================
// om conv: 64 -> 216, one block per (h, b). 512 threads stage A ONCE
// (was 3x redundant across z-tiles) + all 216 B rows; 16 warps split N:
// warps 0-7 -> nt 0..13, warps 8-15 -> nt 14..26, each over its M-tile.
// ===========================================================================
__global__ __launch_bounds__(512, 1) void conv_mma_om_kernel(
    const float* __restrict__ in1,
    const uint32_t* __restrict__ wsp,
    const float* __restrict__ bias, float* __restrict__ out)
{
    constexpr int CIN = 64, COUT = 216, K = CIN * 9, NCH = K / 64;
    constexpr int AW  = 36;                  // words per padded row (144 B)
    constexpr int ALO = 128 * 144;
    constexpr int BHI = 2 * ALO;
    constexpr int BLO = BHI + COUT * 144;

    extern __shared__ char smem[];
    uint32_t sb;
    asm("{ .reg .u64 t; cvta.to.shared.u64 t, %1; cvt.u32.u64 %0, t; }"
        : "=r"(sb) : "l"(smem));
    uint32_t* sw = (uint32_t*)smem;

    const int tid  = threadIdx.x;
    const int lane = tid & 31;
    const int wid  = tid >> 5;               // 0..15
    const int h    = blockIdx.x;
    const int b    = blockIdx.y;

    const int mw = wid & 7;                  // M-tile 0..7
    const int wg = wid >> 3;                 // N-group 0/1

    float acc[14][4];
#pragma unroll
    for (int nt = 0; nt < 14; nt++)
#pragma unroll
        for (int q = 0; q < 4; q++) acc[nt][q] = 0.f;

    const int m0 = mw * 16;
    const uint32_t a_row = (uint32_t)(m0 + ((lane >> 3) & 1) * 8 + (lane & 7));
    const uint32_t a_cw  = (uint32_t)((lane >> 4) * 4);
    const uint32_t aaddr = sb + (a_row * AW + a_cw) * 4;
    const uint32_t b_row = (uint32_t)(lane & 7);
    const uint32_t b_cw  = (uint32_t)(((lane >> 3) & 1) * 4);
    const uint32_t baddr = sb + BHI + (b_row * AW + b_cw) * 4 + wg * 14 * 1152;

    const int jp = tid & 31;                 // k-pair within chunk
    const int mb = tid >> 5;                 // m base 0..15

    for (int kc = 0; kc < NCH; kc++) {
        // ---- stage A once: im2col + bf16 split ----
        {
            int k0 = kc * 64 + 2 * jp, k1 = k0 + 1;
            int ci0 = k0 / 9, r0 = k0 - 9 * ci0, ky0 = r0 / 3, kx0 = r0 - 3 * ky0;
            int ci1 = k1 / 9, r1 = k1 - 9 * ci1, ky1 = r1 / 3, kx1 = r1 - 3 * ky1;
            int gh0 = h - 1 + ky0, gh1 = h - 1 + ky1;
            bool ok0 = (gh0 >= 0) && (gh0 < 128);
            bool ok1 = (gh1 >= 0) && (gh1 < 128);
            const float* p0 = in1 + ((size_t)b * CIN + ci0) * HW + gh0 * 128;
            const float* p1 = in1 + ((size_t)b * CIN + ci1) * HW + gh1 * 128;
#pragma unroll
            for (int mi = 0; mi < 8; mi++) {
                int m  = mb + 16 * mi;
                int g0 = m - 1 + kx0, g1 = m - 1 + kx1;
                float v0 = (ok0 && g0 >= 0 && g0 < 128) ? p0[g0] : 0.f;
                float v1 = (ok1 && g1 >= 0 && g1 < 128) ? p1[g1] : 0.f;
                __nv_bfloat16 h0 = __float2bfloat16(v0);
                __nv_bfloat16 h1 = __float2bfloat16(v1);
                __nv_bfloat16 l0 = __float2bfloat16(v0 - __bfloat162float(h0));
                __nv_bfloat16 l1 = __float2bfloat16(v1 - __bfloat162float(h1));
                sw[m * AW + jp] = (uint32_t)__bfloat16_as_ushort(h0)
                                | ((uint32_t)__bfloat16_as_ushort(h1) << 16);
                sw[(ALO >> 2) + m * AW + jp] = (uint32_t)__bfloat16_as_ushort(l0)
                                | ((uint32_t)__bfloat16_as_ushort(l1) << 16);
            }
        }
        // ---- stage all 216 B rows ----
        for (int idx = tid; idx < COUT * 32; idx += 512) {
            int co = idx >> 5, kp = idx & 31;
            const uint32_t* wp = wsp + (size_t)co * K + kc * 64 + 2 * kp;
            uint32_t e0 = wp[0], e1 = wp[1];
            sw[(BHI >> 2) + co * AW + kp] = (e0 & 0xFFFFu) | (e1 << 16);
            sw[(BLO >> 2) + co * AW + kp] = (e0 >> 16) | (e1 & 0xFFFF0000u);
        }
        __syncthreads();

#pragma unroll
        for (int kt = 0; kt < 4; kt++) {
            uint32_t ah[4], al[4];
            ldm_x4(ah, aaddr + kt * 32);
            ldm_x4(al, aaddr + ALO + kt * 32);
#pragma unroll
            for (int nt = 0; nt < 14; nt++) {
                if (wg * 14 + nt < 27) {
                    uint32_t bh[2], bl[2];
                    ldm_x2(bh, baddr + nt * 1152 + kt * 32);
                    ldm_x2(bl, baddr + (BLO - BHI) + nt * 1152 + kt * 32);
                    mma_bf16(acc[nt], ah, bh);
                    mma_bf16(acc[nt], ah, bl);
                    mma_bf16(acc[nt], al, bh);
                }
            }
        }
        __syncthreads();
    }

    // ---- epilogue ----
    const int mA = m0 + (lane >> 2);
#pragma unroll
    for (int nt = 0; nt < 14; nt++) {
        int ntg = wg * 14 + nt;
        if (ntg < 27) {
            int coA = ntg * 8 + 2 * (lane & 3);
            float ba = bias[coA], bb = bias[coA + 1];
            size_t o00 = ((size_t)b * COUT + coA) * HW + h * 128 + mA;
            out[o00]          = acc[nt][0] + ba;
            out[o00 + HW]     = acc[nt][1] + bb;
            out[o00 + 8]      = acc[nt][2] + ba;
            out[o00 + HW + 8] = acc[nt][3] + bb;
        }
    }
}

// ---------------------------------------------------------------------------
// Generic implicit-GEMM conv (256 threads) — proven R12 version, for em1/em2.
// ---------------------------------------------------------------------------
template<int CIN, int CIN1, int COUT_T, int COUT_TOT, int ACT>
__global__ __launch_bounds__(256, 2) void conv_mma_kernel(
    const float* __restrict__ in1, const float* __restrict__ in2,
    const uint32_t* __restrict__ wsp,
    const float* __restrict__ bias, float* __restrict__ out)
{
    constexpr int K    = CIN * 9;
    constexpr int NCH  = K / 64;
    constexpr int NT8  = COUT_T / 8;
    constexpr int AW   = 36;
    constexpr int ALO  = 128 * 144;
    constexpr int BHI  = 2 * ALO;
    constexpr int BLO  = BHI + COUT_T * 144;

    extern __shared__ char smem[];
    uint32_t sb;
    asm("{ .reg .u64 t; cvta.to.shared.u64 t, %1; cvt.u32.u64 %0, t; }"
        : "=r"(sb) : "l"(smem));
    uint32_t* sw = (uint32_t*)smem;

    const int tid  = threadIdx.x;
    const int lane = tid & 31;
    const int wid  = tid >> 5;
    const int h    = blockIdx.x;
    const int b    = blockIdx.y;
    const int co0  = blockIdx.z * COUT_T;

    float acc[NT8][4];
#pragma unroll
    for (int nt = 0; nt < NT8; nt++)
#pragma unroll
        for (int q = 0; q < 4; q++) acc[nt][q] = 0.f;

    const int m0 = wid * 16;
    const uint32_t a_row = (uint32_t)(m0 + ((lane >> 3) & 1) * 8 + (lane & 7));
    const uint32_t a_cw  = (uint32_t)((lane >> 4) * 4);
    const uint32_t aaddr = sb + (a_row * AW + a_cw) * 4;
    const uint32_t b_row = (uint32_t)(lane & 7);
    const uint32_t b_cw  = (uint32_t)(((lane >> 3) & 1) * 4);
    const uint32_t baddr = sb + BHI + (b_row * AW + b_cw) * 4;

    const int jp = lane;
    const int mb = wid;

    for (int kc = 0; kc < NCH; kc++) {
        {
            int k0 = kc * 64 + 2 * jp, k1 = k0 + 1;
            int ci0 = k0 / 9, r0 = k0 - 9 * ci0, ky0 = r0 / 3, kx0 = r0 - 3 * ky0;
            int ci1 = k1 / 9, r1 = k1 - 9 * ci1, ky1 = r1 / 3, kx1 = r1 - 3 * ky1;
            int gh0 = h - 1 + ky0, gh1 = h - 1 + ky1;
            bool ok0 = (gh0 >= 0) && (gh0 < 128);
            bool ok1 = (gh1 >= 0) && (gh1 < 128);
            const float* p0 = ((ci0 < CIN1)
                ? in1 + ((size_t)b * CIN1 + ci0) * HW
                : in2 + ((size_t)b * (CIN - CIN1) + ci0 - CIN1) * HW) + gh0 * 128;
            const float* p1 = ((ci1 < CIN1)
                ? in1 + ((size_t)b * CIN1 + ci1) * HW
                : in2 + ((size_t)b * (CIN - CIN1) + ci1 - CIN1) * HW) + gh1 * 128;
#pragma unroll
            for (int mi = 0; mi < 16; mi++) {
                int m  = mb + 8 * mi;
                int g0 = m - 1 + kx0, g1 = m - 1 + kx1;
                float v0 = (ok0 && g0 >= 0 && g0 < 128) ? p0[g0] : 0.f;
                float v1 = (ok1 && g1 >= 0 && g1 < 128) ? p1[g1] : 0.f;
                __nv_bfloat16 h0 = __float2bfloat16(v0);
                __nv_bfloat16 h1 = __float2bfloat16(v1);
                __nv_bfloat16 l0 = __float2bfloat16(v0 - __bfloat162float(h0));
                __nv_bfloat16 l1 = __float2bfloat16(v1 - __bfloat162float(h1));
                sw[m * AW + jp] = (uint32_t)__bfloat16_as_ushort(h0)
                                | ((uint32_t)__bfloat16_as_ushort(h1) << 16);
                sw[(ALO >> 2) + m * AW + jp] = (uint32_t)__bfloat16_as_ushort(l0)
                                | ((uint32_t)__bfloat16_as_ushort(l1) << 16);
            }
        }
        for (int idx = tid; idx < COUT_T * 32; idx += 256) {
            int co = idx >> 5, kp = idx & 31;
            const uint32_t* wp = wsp + (size_t)(co0 + co) * K + kc * 64 + 2 * kp;
            uint32_t e0 = wp[0], e1 = wp[1];
            sw[(BHI >> 2) + co * AW + kp] = (e0 & 0xFFFFu) | (e1 << 16);
            sw[(BLO >> 2) + co * AW + kp] = (e0 >> 16) | (e1 & 0xFFFF0000u);
        }
        __syncthreads();

#pragma unroll
        for (int kt = 0; kt < 4; kt++) {
            uint32_t ah[4], al[4];
            ldm_x4(ah, aaddr + kt * 32);
            ldm_x4(al, aaddr + ALO + kt * 32);
#pragma unroll
            for (int nt = 0; nt < NT8; nt++) {
                uint32_t bh[2], bl[2];
                ldm_x2(bh, baddr + nt * 1152 + kt * 32);
                ldm_x2(bl, baddr + (BLO - BHI) + nt * 1152 + kt * 32);
                mma_bf16(acc[nt], ah, bh);
                mma_bf16(acc[nt], ah, bl);
                mma_bf16(acc[nt], al, bh);
            }
        }
        __syncthreads();
    }

    const int mA = m0 + (lane >> 2);
#pragma unroll
    for (int nt = 0; nt < NT8; nt++) {
        int coA = co0 + nt * 8 + 2 * (lane & 3);
        float ba = bias[coA], bb = bias[coA + 1];
        float v[4] = { acc[nt][0] + ba, acc[nt][1] + bb,
                       acc[nt][2] + ba, acc[nt][3] + bb };
#pragma unroll
        for (int q = 0; q < 4; q++) {
            if (ACT == 1) v[q] = (v[q] >= 0.f) ? v[q] : 0.1f * v[q];
            if (ACT == 2) v[q] = 1.f / (1.f + expf(-v[q]));
        }
        size_t o00 = ((size_t)b * COUT_TOT + coA) * HW + h * 128 + mA;
        size_t o01 = o00 + HW;
        out[o00]     = v[0];
        out[o01]     = v[1];
        out[o00 + 8] = v[2];
        out[o01 + 8] = v[3];
    }
}

// ---------------------------------------------------------------------------
// Fused dual modulated deformable conv (DCNv2), stride 1, pad 1. (unchanged)
// ---------------------------------------------------------------------------
__global__ __launch_bounds__(256) void deform_kernel(
    const float* __restrict__ x, const float* __restrict__ s,
    const float* __restrict__ w_dc, const float* __restrict__ b_dc,
    float* __restrict__ out)
{
    __shared__ float s_w[8][8][9];  // [o][c][kk] for this group

    const int tid = threadIdx.x;
    const int b = blockIdx.z >> 3;
    const int g = blockIdx.z & 7;
    const int ty = tid >> 4;
    const int tx = tid & 15;
    const int h  = blockIdx.y * 16 + ty;
    const int wp = blockIdx.x * 16 + tx;

    for (int i = tid; i < 576; i += 256)
        ((float*)s_w)[i] = w_dc[(size_t)g * 576 + i];
    __syncthreads();

    const int pix = h * 128 + wp;
    const float* om_b = g_om + (size_t)b * 216 * HW;
    const float* em_b = g_em + (size_t)b * 72 * HW;
    const float* xb = x + ((size_t)b * 64 + g * 8) * HW;
    const float* sb = s + ((size_t)b * 64 + g * 8) * HW;

    float accx[8], accs[8];
#pragma unroll
    for (int o = 0; o < 8; o++) { accx[o] = 0.f; accs[o] = 0.f; }

    for (int kk = 0; kk < 9; kk++) {
        const int mch = g * 9 + kk;
        float dy   = om_b[(size_t)(2 * mch) * HW + pix];
        float dx   = om_b[(size_t)(2 * mch + 1) * HW + pix];
        float mraw = om_b[(size_t)(144 + mch) * HW + pix];
        float mx = 1.f / (1.f + expf(-mraw));
        float me = em_b[(size_t)mch * HW + pix];

        float py = (float)(h - 1 + kk / 3) + dy;
        float px = (float)(wp - 1 + kk % 3) + dx;
        float y0f = floorf(py), x0f = floorf(px);
        int y0 = (int)y0f, x0 = (int)x0f;
        float ly = py - y0f, lx = px - x0f;
        int y1 = y0 + 1, x1 = x0 + 1;

        float vy0 = (y0 >= 0 && y0 < 128) ? 1.f : 0.f;
        float vy1 = (y1 >= 0 && y1 < 128) ? 1.f : 0.f;
        float vx0 = (x0 >= 0 && x0 < 128) ? 1.f : 0.f;
        float vx1 = (x1 >= 0 && x1 < 128) ? 1.f : 0.f;

        float w00 = (1.f - ly) * (1.f - lx) * vy0 * vx0;
        float w01 = (1.f - ly) * lx         * vy0 * vx1;
        float w10 = ly * (1.f - lx)         * vy1 * vx0;
        float w11 = ly * lx                 * vy1 * vx1;

        int cy0 = min(max(y0, 0), 127), cy1 = min(max(y1, 0), 127);
        int cx0 = min(max(x0, 0), 127), cx1 = min(max(x1, 0), 127);
        int i00 = cy0 * 128 + cx0, i01 = cy0 * 128 + cx1;
        int i10 = cy1 * 128 + cx0, i11 = cy1 * 128 + cx1;

#pragma unroll
        for (int c = 0; c < 8; c++) {
            const float* xp = xb + (size_t)c * HW;
            const float* sp = sb + (size_t)c * HW;
            float vx = w00 * xp[i00] + w01 * xp[i01] + w10 * xp[i10] + w11 * xp[i11];
            float vs = w00 * sp[i00] + w01 * sp[i01] + w10 * sp[i10] + w11 * sp[i11];
            float ax  = vx * mx;
            float as_ = vs * me;
#pragma unroll
            for (int o = 0; o < 8; o++) {
                float wv = s_w[o][c][kk];
                accx[o] += ax * wv;
                accs[o] += as_ * wv;
            }
        }
    }

#pragma unroll
    for (int o = 0; o < 8; o++) {
        float bs = b_dc[g * 8 + o];
        size_t oidx = ((size_t)b * 64 + g * 8 + o) * HW + pix;
        out[oidx] = accx[o] + bs;
        out[(size_t)4 * 64 * HW + oidx] = accs[o] + bs;
    }
}

extern "C" void kernel_launch(void* const* d_in, const int* in_sizes, int n_in,
                              void* d_out, int out_size)
{
    const float* x     = (const float*)d_in[0];
    const float* shf   = (const float*)d_in[1];
    const float* off   = (const float*)d_in[2];
    const float* w_om  = (const float*)d_in[3];
    const float* b_om  = (const float*)d_in[4];
    const float* w_em1 = (const float*)d_in[5];
    const float* b_em1 = (const float*)d_in[6];
    const float* w_em2 = (const float*)d_in[7];
    const float* b_em2 = (const float*)d_in[8];
    const float* w_dc  = (const float*)d_in[9];
    const float* b_dc  = (const float*)d_in[10];
    float* out = (float*)d_out;

    float *p_om, *p_em1, *p_em;
    uint32_t *pw_om, *pw_em1, *pw_em2;
    cudaGetSymbolAddress((void**)&p_om,  g_om);
    cudaGetSymbolAddress((void**)&p_em1, g_em1);
    cudaGetSymbolAddress((void**)&p_em,  g_em);
    cudaGetSymbolAddress((void**)&pw_om,  g_w_om);
    cudaGetSymbolAddress((void**)&pw_em1, g_w_em1);
    cudaGetSymbolAddress((void**)&pw_em2, g_w_em2);

    const int SM_OM = 36864 + 2 * 216 * 144;  // 99072 (512-thread om)
    const int SM_72 = 36864 + 2 * 72 * 144;   // 57600
    const int SM_64 = 36864 + 2 * 64 * 144;   // 55296
    cudaFuncSetAttribute(conv_mma_om_kernel,
                         cudaFuncAttributeMaxDynamicSharedMemorySize, SM_OM);
    cudaFuncSetAttribute(conv_mma_kernel<128, 64, 64, 64, 1>,
                         cudaFuncAttributeMaxDynamicSharedMemorySize, SM_64);
    cudaFuncSetAttribute(conv_mma_kernel<64, 64, 72, 72, 2>,
                         cudaFuncAttributeMaxDynamicSharedMemorySize, SM_72);

    // split weights into bf16 (hi,lo) pairs
    wsplit_kernel<<<(216 *  576 + 255) / 256, 256>>>(w_om,  pw_om,  216 *  576);
    wsplit_kernel<<<( 64 * 1152 + 255) / 256, 256>>>(w_em1, pw_em1,  64 * 1152);
    wsplit_kernel<<<( 72 *  576 + 255) / 256, 256>>>(w_em2, pw_em2,  72 *  576);

    // om = conv3x3(offset_feat) : 64 -> 216 (single-pass A staging, 512 thr)
    conv_mma_om_kernel<<<dim3(128, 4), 512, SM_OM>>>(off, pw_om, b_om, p_om);

    // em1 = leaky(conv3x3(concat(share, offset_feat))) : 128 -> 64
    conv_mma_kernel<128, 64, 64, 64, 1><<<dim3(128, 4, 1), 256, SM_64>>>(
        shf, off, pw_em1, b_em1, p_em1);

    // em = sigmoid(conv3x3(em1)) : 64 -> 72
    conv_mma_kernel<64, 64, 72, 72, 2><<<dim3(128, 4, 1), 256, SM_72>>>(
        p_em1, p_em1, pw_em2, b_em2, p_em);

    // both deformable convs fused (shared offsets + weights)
    deform_kernel<<<dim3(8, 8, 32), 256>>>(x, shf, w_dc, b_dc, out);
}

// round 14
// speedup vs baseline: 3.0393x; 1.2911x over previous
#include <cuda_runtime.h>
#include <cuda_bf16.h>
#include <math.h>
#include <stdint.h>

#define HW 16384
#define PLN (128 * 136)          // padded plane elems per (b,ci)

// fp32 scratch (module-load allocated, legal per harness rules)
__device__ float g_om [4 * 216 * HW];
__device__ float g_em1[4 *  64 * HW];
__device__ float g_em [4 *  72 * HW];

// Pre-split inputs: 3 kx-shifted zero-padded bf16 planes, hi & lo.
// layout [s][b*ci][h][136], row stride 272B (16B-aligned).
__device__ __nv_bfloat16 g_off_hi[3 * 4 * 64 * PLN];
__device__ __nv_bfloat16 g_off_lo[3 * 4 * 64 * PLN];
__device__ __nv_bfloat16 g_shf_hi[3 * 4 * 64 * PLN];
__device__ __nv_bfloat16 g_shf_lo[3 * 4 * 64 * PLN];
__device__ __nv_bfloat16 g_e1_hi [3 * 4 * 64 * PLN];
__device__ __nv_bfloat16 g_e1_lo [3 * 4 * 64 * PLN];

// Pre-split weights (separate hi/lo bf16, K-major [co][Cin*9])
__device__ __nv_bfloat16 g_wh_om [216 *  576];
__device__ __nv_bfloat16 g_wl_om [216 *  576];
__device__ __nv_bfloat16 g_wh_em1[ 64 * 1152];
__device__ __nv_bfloat16 g_wl_em1[ 64 * 1152];
__device__ __nv_bfloat16 g_wh_em2[ 72 *  576];
__device__ __nv_bfloat16 g_wl_em2[ 72 *  576];

// ---------------------------------------------------------------------------
__global__ void wsplit2_kernel(const float* __restrict__ w,
                               __nv_bfloat16* __restrict__ hi,
                               __nv_bfloat16* __restrict__ lo, int n)
{
    int i = blockIdx.x * 256 + threadIdx.x;
    if (i >= n) return;
    float x = w[i];
    __nv_bfloat16 h = __float2bfloat16(x);
    hi[i] = h;
    lo[i] = __float2bfloat16(x - __bfloat162float(h));
}

// presplit input into 3 shifted padded bf16 hi/lo planes
__global__ void psplit_kernel(const float* __restrict__ src,
                              __nv_bfloat16* __restrict__ hi,
                              __nv_bfloat16* __restrict__ lo, int nbc)
{
    int h = blockIdx.x, bc = blockIdx.y, m = threadIdx.x;
    if (m >= 136) return;
    const float* row = src + (size_t)bc * HW + h * 128;
    size_t S = (size_t)nbc * PLN;
#pragma unroll
    for (int s = 0; s < 3; s++) {
        int g = m - 1 + s;
        float v = (g >= 0 && g < 128) ? row[g] : 0.f;
        __nv_bfloat16 hv = __float2bfloat16(v);
        __nv_bfloat16 lv = __float2bfloat16(v - __bfloat162float(hv));
        size_t o = (size_t)s * S + ((size_t)bc * 128 + h) * 136 + m;
        hi[o] = hv;
        lo[o] = lv;
    }
}

// ---------------------------------------------------------------------------
// warp-mma helpers (baseline PTX, valid at compute_103)
// ---------------------------------------------------------------------------
__device__ __forceinline__ void ldm_x4t(uint32_t* r, uint32_t addr) {
    asm volatile("ldmatrix.sync.aligned.m8n8.x4.trans.shared.b16 {%0,%1,%2,%3}, [%4];"
        : "=r"(r[0]), "=r"(r[1]), "=r"(r[2]), "=r"(r[3]) : "r"(addr));
}
__device__ __forceinline__ void ldm_x2(uint32_t* r, uint32_t addr) {
    asm volatile("ldmatrix.sync.aligned.m8n8.x2.shared.b16 {%0,%1}, [%2];"
        : "=r"(r[0]), "=r"(r[1]) : "r"(addr));
}
__device__ __forceinline__ void mma_bf16(float* c, const uint32_t* a, const uint32_t* b) {
    asm volatile("mma.sync.aligned.m16n8k16.row.col.f32.bf16.bf16.f32 "
        "{%0,%1,%2,%3},{%4,%5,%6,%7},{%8,%9},{%0,%1,%2,%3};"
        : "+f"(c[0]), "+f"(c[1]), "+f"(c[2]), "+f"(c[3])
        : "r"(a[0]), "r"(a[1]), "r"(a[2]), "r"(a[3]), "r"(b[0]), "r"(b[1]));
}

// ===========================================================================
// Implicit-GEMM conv3x3 on mma.sync bf16 3-pass, cp.async double-buffered.
// 512 threads; M=128 pixels (image row h); 16 warps = 8 M-tiles x 2 N-groups
// (group0 = NTG0 nt, group1 = NT_TOT-NTG0). A staged k-major (272B rows) via
// 16B cp.async from pre-split shifted planes (zfill for invalid gh); loaded
// via ldmatrix.x4.trans. B staged n-major (144B rows) via 16B cp.async.
// ===========================================================================
template<int CIN, int CIN1, int COUT, int NTG0, int ACT>
__global__ __launch_bounds__(512, 1) void conv_ps_kernel(
    const __nv_bfloat16* __restrict__ p1hi, const __nv_bfloat16* __restrict__ p1lo,
    const __nv_bfloat16* __restrict__ p2hi, const __nv_bfloat16* __restrict__ p2lo,
    const __nv_bfloat16* __restrict__ whi,  const __nv_bfloat16* __restrict__ wlo,
    const float* __restrict__ bias, float* __restrict__ out)
{
    constexpr int K      = CIN * 9;
    constexpr int NCH    = K / 64;
    constexpr int NT_TOT = (COUT + 7) / 8;
    constexpr int CIN2   = CIN - CIN1;
    constexpr size_t S1  = (size_t)4 * CIN1 * PLN;
    constexpr size_t S2  = (size_t)4 * (CIN2 ? CIN2 : 1) * PLN;
    constexpr int ASZ    = 2 * 64 * 272;        // hi+lo per buf = 34816 B
    constexpr int BB     = 2 * ASZ;             // B region base = 69632
    constexpr int BSZ    = 2 * COUT * 144;      // hi+lo per buf

    extern __shared__ char smem[];
    uint32_t sb;
    asm("{ .reg .u64 t; cvta.to.shared.u64 t, %1; cvt.u32.u64 %0, t; }"
        : "=r"(sb) : "l"(smem));

    const int tid  = threadIdx.x;
    const int lane = tid & 31;
    const int wid  = tid >> 5;
    const int h    = blockIdx.x;
    const int b    = blockIdx.y;

    const int mw = wid & 7;            // M-tile
    const int wg = wid >> 3;           // N-group
    const int m0 = mw * 16;
    const int ntc = wg ? (NT_TOT - NTG0) : NTG0;
    const int ntb = wg * NTG0;

    float acc[NTG0][4];
#pragma unroll
    for (int nt = 0; nt < NTG0; nt++)
#pragma unroll
        for (int q = 0; q < 4; q++) acc[nt][q] = 0.f;

    // ldmatrix lane offsets
    const uint32_t a_k  = (uint32_t)(((lane >> 4) << 3) + (lane & 7));
    const uint32_t a_m  = (uint32_t)(m0 + (((lane >> 3) & 1) << 3));
    const uint32_t aoff = a_k * 272 + a_m * 2;
    const uint32_t boff = (uint32_t)((lane & 7) * 144 + ((lane >> 3) & 1) * 16);

    auto stage = [&](int kc, int buf) {
        // A: 2 planes x 64 k-rows x 16 chunks of 16B = 2048 copies
#pragma unroll
        for (int i = 0; i < 4; i++) {
            int idx = tid + 512 * i;
            int pl  = idx >> 10;
            int rem = idx & 1023;
            int kr  = rem >> 4;
            int ch  = rem & 15;
            int k  = kc * 64 + kr;
            int ci = k / 9, r = k - 9 * ci, ky = r / 3, kx = r - 3 * ky;
            int gh = h - 1 + ky;
            int sz = ((unsigned)gh < 128u) ? 16 : 0;
            int ghc = min(max(gh, 0), 127);
            const __nv_bfloat16* base;
            if (ci < CIN1)
                base = (pl ? p1lo : p1hi) + (size_t)kx * S1
                     + ((size_t)(b * CIN1 + ci) * 128 + ghc) * 136;
            else
                base = (pl ? p2lo : p2hi) + (size_t)kx * S2
                     + ((size_t)(b * CIN2 + (ci - CIN1)) * 128 + ghc) * 136;
            const char* src = (const char*)base + ch * 16;
            uint32_t dst = sb + buf * ASZ + pl * 17408 + kr * 272 + ch * 16;
            asm volatile("cp.async.cg.shared.global [%0], [%1], 16, %2;"
                         :: "r"(dst), "l"(src), "r"(sz));
        }
        // B: 2 planes x COUT rows x 8 chunks
        for (int idx = tid; idx < COUT * 16; idx += 512) {
            int pl  = (idx >= COUT * 8) ? 1 : 0;
            int rem = idx - pl * COUT * 8;
            int co  = rem >> 3;
            int ch  = rem & 7;
            const __nv_bfloat16* w = pl ? wlo : whi;
            const char* src = (const char*)(w + (size_t)co * K + kc * 64) + ch * 16;
            uint32_t dst = sb + BB + buf * BSZ + pl * (COUT * 144) + co * 144 + ch * 16;
            asm volatile("cp.async.cg.shared.global [%0], [%1], 16, 16;"
                         :: "r"(dst), "l"(src));
        }
        asm volatile("cp.async.commit_group;" ::: "memory");
    };

    stage(0, 0);

    int buf = 0;
    for (int kc = 0; kc < NCH; kc++, buf ^= 1) {
        if (kc + 1 < NCH) {
            stage(kc + 1, buf ^ 1);
            asm volatile("cp.async.wait_group 1;" ::: "memory");
        } else {
            asm volatile("cp.async.wait_group 0;" ::: "memory");
        }
        __syncthreads();

        uint32_t Ab = sb + buf * ASZ;
        uint32_t Bb = sb + BB + buf * BSZ;
#pragma unroll
        for (int kt = 0; kt < 4; kt++) {
            uint32_t ah[4], al[4];
            ldm_x4t(ah, Ab + kt * 4352 + aoff);
            ldm_x4t(al, Ab + 17408 + kt * 4352 + aoff);
#pragma unroll
            for (int nt = 0; nt < NTG0; nt++) {
                if (nt < ntc) {
                    uint32_t bh[2], bl[2];
                    ldm_x2(bh, Bb + (ntb + nt) * 1152 + boff + kt * 32);
                    ldm_x2(bl, Bb + COUT * 144 + (ntb + nt) * 1152 + boff + kt * 32);
                    mma_bf16(acc[nt], ah, bh);
                    mma_bf16(acc[nt], ah, bl);
                    mma_bf16(acc[nt], al, bh);
                }
            }
        }
        __syncthreads();
    }

    // epilogue
    const int mA = m0 + (lane >> 2);
#pragma unroll
    for (int nt = 0; nt < NTG0; nt++) {
        if (nt < ntc) {
            int coA = (ntb + nt) * 8 + 2 * (lane & 3);
            float ba = bias[coA], bb = bias[coA + 1];
            float v[4] = { acc[nt][0] + ba, acc[nt][1] + bb,
                           acc[nt][2] + ba, acc[nt][3] + bb };
#pragma unroll
            for (int q = 0; q < 4; q++) {
                if (ACT == 1) v[q] = (v[q] >= 0.f) ? v[q] : 0.1f * v[q];
                if (ACT == 2) v[q] = 1.f / (1.f + expf(-v[q]));
            }
            size_t o00 = ((size_t)b * COUT + coA) * HW + h * 128 + mA;
            out[o00]          = v[0];
            out[o00 + HW]     = v[1];
            out[o00 + 8]      = v[2];
            out[o00 + HW + 8] = v[3];
        }
    }
}

// ---------------------------------------------------------------------------
// Fused dual modulated deformable conv (DCNv2), stride 1, pad 1. (unchanged)
// ---------------------------------------------------------------------------
__global__ __launch_bounds__(256) void deform_kernel(
    const float* __restrict__ x, const float* __restrict__ s,
    const float* __restrict__ w_dc, const float* __restrict__ b_dc,
    float* __restrict__ out)
{
    __shared__ float s_w[8][8][9];

    const int tid = threadIdx.x;
    const int b = blockIdx.z >> 3;
    const int g = blockIdx.z & 7;
    const int ty = tid >> 4;
    const int tx = tid & 15;
    const int h  = blockIdx.y * 16 + ty;
    const int wp = blockIdx.x * 16 + tx;

    for (int i = tid; i < 576; i += 256)
        ((float*)s_w)[i] = w_dc[(size_t)g * 576 + i];
    __syncthreads();

    const int pix = h * 128 + wp;
    const float* om_b = g_om + (size_t)b * 216 * HW;
    const float* em_b = g_em + (size_t)b * 72 * HW;
    const float* xb = x + ((size_t)b * 64 + g * 8) * HW;
    const float* sb = s + ((size_t)b * 64 + g * 8) * HW;

    float accx[8], accs[8];
#pragma unroll
    for (int o = 0; o < 8; o++) { accx[o] = 0.f; accs[o] = 0.f; }

    for (int kk = 0; kk < 9; kk++) {
        const int mch = g * 9 + kk;
        float dy   = om_b[(size_t)(2 * mch) * HW + pix];
        float dx   = om_b[(size_t)(2 * mch + 1) * HW + pix];
        float mraw = om_b[(size_t)(144 + mch) * HW + pix];
        float mx = 1.f / (1.f + expf(-mraw));
        float me = em_b[(size_t)mch * HW + pix];

        float py = (float)(h - 1 + kk / 3) + dy;
        float px = (float)(wp - 1 + kk % 3) + dx;
        float y0f = floorf(py), x0f = floorf(px);
        int y0 = (int)y0f, x0 = (int)x0f;
        float ly = py - y0f, lx = px - x0f;
        int y1 = y0 + 1, x1 = x0 + 1;

        float vy0 = (y0 >= 0 && y0 < 128) ? 1.f : 0.f;
        float vy1 = (y1 >= 0 && y1 < 128) ? 1.f : 0.f;
        float vx0 = (x0 >= 0 && x0 < 128) ? 1.f : 0.f;
        float vx1 = (x1 >= 0 && x1 < 128) ? 1.f : 0.f;

        float w00 = (1.f - ly) * (1.f - lx) * vy0 * vx0;
        float w01 = (1.f - ly) * lx         * vy0 * vx1;
        float w10 = ly * (1.f - lx)         * vy1 * vx0;
        float w11 = ly * lx                 * vy1 * vx1;

        int cy0 = min(max(y0, 0), 127), cy1 = min(max(y1, 0), 127);
        int cx0 = min(max(x0, 0), 127), cx1 = min(max(x1, 0), 127);
        int i00 = cy0 * 128 + cx0, i01 = cy0 * 128 + cx1;
        int i10 = cy1 * 128 + cx0, i11 = cy1 * 128 + cx1;

#pragma unroll
        for (int c = 0; c < 8; c++) {
            const float* xp = xb + (size_t)c * HW;
            const float* sp = sb + (size_t)c * HW;
            float vx = w00 * xp[i00] + w01 * xp[i01] + w10 * xp[i10] + w11 * xp[i11];
            float vs = w00 * sp[i00] + w01 * sp[i01] + w10 * sp[i10] + w11 * sp[i11];
            float ax  = vx * mx;
            float as_ = vs * me;
#pragma unroll
            for (int o = 0; o < 8; o++) {
                float wv = s_w[o][c][kk];
                accx[o] += ax * wv;
                accs[o] += as_ * wv;
            }
        }
    }

#pragma unroll
    for (int o = 0; o < 8; o++) {
        float bs = b_dc[g * 8 + o];
        size_t oidx = ((size_t)b * 64 + g * 8 + o) * HW + pix;
        out[oidx] = accx[o] + bs;
        out[(size_t)4 * 64 * HW + oidx] = accs[o] + bs;
    }
}

extern "C" void kernel_launch(void* const* d_in, const int* in_sizes, int n_in,
                              void* d_out, int out_size)
{
    const float* x     = (const float*)d_in[0];
    const float* shf   = (const float*)d_in[1];
    const float* off   = (const float*)d_in[2];
    const float* w_om  = (const float*)d_in[3];
    const float* b_om  = (const float*)d_in[4];
    const float* w_em1 = (const float*)d_in[5];
    const float* b_em1 = (const float*)d_in[6];
    const float* w_em2 = (const float*)d_in[7];
    const float* b_em2 = (const float*)d_in[8];
    const float* w_dc  = (const float*)d_in[9];
    const float* b_dc  = (const float*)d_in[10];
    float* out = (float*)d_out;

    float *p_om, *p_em1, *p_em;
    cudaGetSymbolAddress((void**)&p_om,  g_om);
    cudaGetSymbolAddress((void**)&p_em1, g_em1);
    cudaGetSymbolAddress((void**)&p_em,  g_em);

    __nv_bfloat16 *offh, *offl, *shfh, *shfl, *e1h, *e1l;
    cudaGetSymbolAddress((void**)&offh, g_off_hi);
    cudaGetSymbolAddress((void**)&offl, g_off_lo);
    cudaGetSymbolAddress((void**)&shfh, g_shf_hi);
    cudaGetSymbolAddress((void**)&shfl, g_shf_lo);
    cudaGetSymbolAddress((void**)&e1h,  g_e1_hi);
    cudaGetSymbolAddress((void**)&e1l,  g_e1_lo);

    __nv_bfloat16 *whom, *wlom, *whe1, *wle1, *whe2, *wle2;
    cudaGetSymbolAddress((void**)&whom, g_wh_om);
    cudaGetSymbolAddress((void**)&wlom, g_wl_om);
    cudaGetSymbolAddress((void**)&whe1, g_wh_em1);
    cudaGetSymbolAddress((void**)&wle1, g_wl_em1);
    cudaGetSymbolAddress((void**)&whe2, g_wh_em2);
    cudaGetSymbolAddress((void**)&wle2, g_wl_em2);

    const int SM_OM  = 69632 + 2 * 2 * 216 * 144;  // 194048
    const int SM_EM1 = 69632 + 2 * 2 *  64 * 144;  // 106496
    const int SM_EM2 = 69632 + 2 * 2 *  72 * 144;  // 111104
    cudaFuncSetAttribute(conv_ps_kernel<64, 64, 216, 14, 0>,
                         cudaFuncAttributeMaxDynamicSharedMemorySize, SM_OM);
    cudaFuncSetAttribute(conv_ps_kernel<128, 64, 64, 4, 1>,
                         cudaFuncAttributeMaxDynamicSharedMemorySize, SM_EM1);
    cudaFuncSetAttribute(conv_ps_kernel<64, 64, 72, 5, 2>,
                         cudaFuncAttributeMaxDynamicSharedMemorySize, SM_EM2);

    // pre-split weights + inputs
    wsplit2_kernel<<<(216 *  576 + 255) / 256, 256>>>(w_om,  whom, wlom, 216 *  576);
    wsplit2_kernel<<<( 64 * 1152 + 255) / 256, 256>>>(w_em1, whe1, wle1,  64 * 1152);
    wsplit2_kernel<<<( 72 *  576 + 255) / 256, 256>>>(w_em2, whe2, wle2,  72 *  576);
    psplit_kernel<<<dim3(128, 256), 160>>>(off, offh, offl, 256);
    psplit_kernel<<<dim3(128, 256), 160>>>(shf, shfh, shfl, 256);

    // om = conv3x3(offset_feat) : 64 -> 216
    conv_ps_kernel<64, 64, 216, 14, 0><<<dim3(128, 4), 512, SM_OM>>>(
        offh, offl, offh, offl, whom, wlom, b_om, p_om);

    // em1 = leaky(conv3x3(concat(share, offset_feat))) : 128 -> 64
    conv_ps_kernel<128, 64, 64, 4, 1><<<dim3(128, 4), 512, SM_EM1>>>(
        shfh, shfl, offh, offl, whe1, wle1, b_em1, p_em1);

    // presplit em1 output, then em2
    psplit_kernel<<<dim3(128, 256), 160>>>(p_em1, e1h, e1l, 256);

    // em = sigmoid(conv3x3(em1)) : 64 -> 72
    conv_ps_kernel<64, 64, 72, 5, 2><<<dim3(128, 4), 512, SM_EM2>>>(
        e1h, e1l, e1h, e1l, whe2, wle2, b_em2, p_em);

    // both deformable convs fused (shared offsets + weights)
    deform_kernel<<<dim3(8, 8, 32), 256>>>(x, shf, w_dc, b_dc, out);
}